// round 2
// baseline (speedup 1.0000x reference)
#include <cuda_runtime.h>
#include <math.h>
#include <math_constants.h>

#define BB 4
#define SS 2048
#define EE 1024
#define HH 16
#define DD 64
#define MROWS (BB*SS)          // 8192

// -------- device scratch (statically allocated; no cudaMalloc allowed) -----
__device__ float g_q[8388608];          // [B,H,S,D]
__device__ float g_k[8388608];          // [B,H,S,D]
__device__ float g_v[8388608];          // [B,H,S,D]
__device__ float g_att[8388608];        // [B,S,E]  (pre out-proj)
__device__ float g_p[268435456];        // [B,H,S,S] scores / probs (1 GB)

// ---------------------------------------------------------------------------
// proj: C[m,n] = sum_k X[m,k]*W[n,k] + bias[n]
//   mode 0: plain row-major [M,E] output
//   mode 1: head layout [B,H,S,D]
//   mode 2: head layout + RoPE
// 64x64 tile, BK=16, 256 threads, 4x4 microtile, both smem operands
// stored k-major so compute loads are LDS.128.
// ---------------------------------------------------------------------------
__global__ void proj_kernel(const float* __restrict__ X,
                            const float* __restrict__ W,
                            const float* __restrict__ bias,
                            float* __restrict__ out, int mode)
{
    __shared__ float Ast[16][68];
    __shared__ float Wst[16][68];
    const int tid = threadIdx.x;
    const int tx = tid & 15, ty = tid >> 4;
    const int row0 = blockIdx.y * 64;
    const int col0 = blockIdx.x * 64;

    const int lr = tid >> 2;          // 0..63
    const int lc = (tid & 3) << 2;    // 0,4,8,12

    float acc[4][4] = {};

    for (int k0 = 0; k0 < EE; k0 += 16) {
        float4 a4 = *(const float4*)(X + (size_t)(row0 + lr) * EE + k0 + lc);
        float4 w4 = *(const float4*)(W + (size_t)(col0 + lr) * EE + k0 + lc);
        Ast[lc + 0][lr] = a4.x; Ast[lc + 1][lr] = a4.y;
        Ast[lc + 2][lr] = a4.z; Ast[lc + 3][lr] = a4.w;
        Wst[lc + 0][lr] = w4.x; Wst[lc + 1][lr] = w4.y;
        Wst[lc + 2][lr] = w4.z; Wst[lc + 3][lr] = w4.w;
        __syncthreads();
        #pragma unroll
        for (int k = 0; k < 16; k++) {
            float4 av = *(const float4*)&Ast[k][ty << 2];
            float4 bv = *(const float4*)&Wst[k][tx << 2];
            float a[4] = {av.x, av.y, av.z, av.w};
            float b[4] = {bv.x, bv.y, bv.z, bv.w};
            #pragma unroll
            for (int i = 0; i < 4; i++)
                #pragma unroll
                for (int j = 0; j < 4; j++)
                    acc[i][j] = fmaf(a[i], b[j], acc[i][j]);
        }
        __syncthreads();
    }

    const int n0 = col0 + (tx << 2);
    const float b0 = bias[n0 + 0], b1 = bias[n0 + 1];
    const float b2 = bias[n0 + 2], b3 = bias[n0 + 3];

    #pragma unroll
    for (int i = 0; i < 4; i++) {
        const int m = row0 + (ty << 2) + i;
        float vals[4] = {acc[i][0] + b0, acc[i][1] + b1,
                         acc[i][2] + b2, acc[i][3] + b3};
        if (mode == 0) {
            *(float4*)(out + (size_t)m * EE + n0) =
                make_float4(vals[0], vals[1], vals[2], vals[3]);
        } else {
            const int bidx = m / SS, spos = m % SS;
            const int h = n0 >> 6, d0 = n0 & 63;
            if (mode == 2) {
                #pragma unroll
                for (int pr = 0; pr < 2; pr++) {
                    const int p = (d0 >> 1) + pr;   // pair index 0..31
                    // inv_freq = 10000^(-2p/64) = exp(-p * 2*ln(10000)/64)
                    const float inv = expf(-(float)p * 0.28782313662425567f);
                    const float ang = (float)spos * inv;
                    float sn, cs;
                    sincosf(ang, &sn, &cs);
                    const float v0 = vals[2 * pr], v1 = vals[2 * pr + 1];
                    vals[2 * pr]     = v0 * cs - v1 * sn;
                    vals[2 * pr + 1] = v1 * cs + v0 * sn;
                }
            }
            *(float4*)(out + (((size_t)(bidx * HH + h) * SS + spos) * DD + d0)) =
                make_float4(vals[0], vals[1], vals[2], vals[3]);
        }
    }
}

// ---------------------------------------------------------------------------
// scores: P[bh,q,k] = scale * sum_d Q[bh,q,d]*K[bh,k,d]
// grid (S/64, S/64, B*H); K-dim = 64 fully resident in smem (transposed).
// ---------------------------------------------------------------------------
__global__ void scores_kernel(const float* __restrict__ Q,
                              const float* __restrict__ K,
                              float* __restrict__ P)
{
    __shared__ float Qst[64][68];   // [d][q]
    __shared__ float Kst[64][68];   // [d][k]
    const int tid = threadIdx.x;
    const int tx = tid & 15, ty = tid >> 4;
    const int bh = blockIdx.z;
    const int q0 = blockIdx.y * 64;
    const int k0 = blockIdx.x * 64;
    const size_t base = (size_t)bh * SS * DD;

    for (int t = tid; t < 1024; t += 256) {
        const int r = t >> 4;
        const int c = (t & 15) << 2;
        float4 qv = *(const float4*)(Q + base + (size_t)(q0 + r) * DD + c);
        float4 kv = *(const float4*)(K + base + (size_t)(k0 + r) * DD + c);
        Qst[c + 0][r] = qv.x; Qst[c + 1][r] = qv.y;
        Qst[c + 2][r] = qv.z; Qst[c + 3][r] = qv.w;
        Kst[c + 0][r] = kv.x; Kst[c + 1][r] = kv.y;
        Kst[c + 2][r] = kv.z; Kst[c + 3][r] = kv.w;
    }
    __syncthreads();

    float acc[4][4] = {};
    #pragma unroll 16
    for (int k = 0; k < 64; k++) {
        float4 av = *(const float4*)&Qst[k][ty << 2];
        float4 bv = *(const float4*)&Kst[k][tx << 2];
        float a[4] = {av.x, av.y, av.z, av.w};
        float b[4] = {bv.x, bv.y, bv.z, bv.w};
        #pragma unroll
        for (int i = 0; i < 4; i++)
            #pragma unroll
            for (int j = 0; j < 4; j++)
                acc[i][j] = fmaf(a[i], b[j], acc[i][j]);
    }

    const size_t pbase = (size_t)bh * SS * SS;
    #pragma unroll
    for (int i = 0; i < 4; i++) {
        *(float4*)(P + pbase + (size_t)(q0 + (ty << 2) + i) * SS + k0 + (tx << 2)) =
            make_float4(acc[i][0] * 0.125f, acc[i][1] * 0.125f,
                        acc[i][2] * 0.125f, acc[i][3] * 0.125f);
    }
}

// ---------------------------------------------------------------------------
// softmax over last dim (2048), in place. One block per row, regs-resident.
// ---------------------------------------------------------------------------
__global__ void softmax_kernel(float* __restrict__ P)
{
    const size_t row = blockIdx.x;
    float* p = P + row * (size_t)SS;
    const int tid = threadIdx.x;
    const int lane = tid & 31, warp = tid >> 5;
    __shared__ float red[8];

    float v[8];
    #pragma unroll
    for (int i = 0; i < 8; i++) v[i] = p[tid + (i << 8)];

    float m = v[0];
    #pragma unroll
    for (int i = 1; i < 8; i++) m = fmaxf(m, v[i]);
    #pragma unroll
    for (int o = 16; o; o >>= 1) m = fmaxf(m, __shfl_xor_sync(0xffffffffu, m, o));
    if (lane == 0) red[warp] = m;
    __syncthreads();
    if (tid < 32) {
        float t = (tid < 8) ? red[tid] : -CUDART_INF_F;
        #pragma unroll
        for (int o = 4; o; o >>= 1) t = fmaxf(t, __shfl_xor_sync(0xffffffffu, t, o));
        if (tid == 0) red[0] = t;
    }
    __syncthreads();
    m = red[0];
    __syncthreads();

    float sum = 0.f;
    #pragma unroll
    for (int i = 0; i < 8; i++) { v[i] = expf(v[i] - m); sum += v[i]; }
    #pragma unroll
    for (int o = 16; o; o >>= 1) sum += __shfl_xor_sync(0xffffffffu, sum, o);
    if (lane == 0) red[warp] = sum;
    __syncthreads();
    if (tid < 32) {
        float t = (tid < 8) ? red[tid] : 0.f;
        #pragma unroll
        for (int o = 4; o; o >>= 1) t += __shfl_xor_sync(0xffffffffu, t, o);
        if (tid == 0) red[0] = t;
    }
    __syncthreads();
    const float inv = 1.0f / red[0];
    #pragma unroll
    for (int i = 0; i < 8; i++) p[tid + (i << 8)] = v[i] * inv;
}

// ---------------------------------------------------------------------------
// mean over heads: wout[b,q,k] = (1/16) sum_h P[b,h,q,k]
// ---------------------------------------------------------------------------
__global__ void mean_kernel(const float* __restrict__ P, float* __restrict__ wout)
{
    const int bq = blockIdx.x;          // 0 .. B*S-1
    const int b = bq / SS, q = bq % SS;
    const size_t base0 = (size_t)b * HH * SS * SS + (size_t)q * SS;
    for (int k = threadIdx.x; k < SS; k += 256) {
        float s = 0.f;
        #pragma unroll
        for (int h = 0; h < HH; h++)
            s += P[base0 + (size_t)h * SS * SS + k];
        wout[(size_t)bq * SS + k] = s * (1.0f / HH);
    }
}

// ---------------------------------------------------------------------------
// attn @ V: Oatt[b,q,h*64+d] = sum_k P[bh,q,k]*V[bh,k,d]
// grid (S/64, B*H); BK=32; P transposed in smem, V direct.
// ---------------------------------------------------------------------------
__global__ void av_kernel(const float* __restrict__ P,
                          const float* __restrict__ V,
                          float* __restrict__ Oatt)
{
    __shared__ float Pst[32][68];   // [k][q]
    __shared__ float Vs[32][68];    // [k][d]
    const int tid = threadIdx.x;
    const int tx = tid & 15, ty = tid >> 4;
    const int bh = blockIdx.y;
    const int b = bh >> 4, h = bh & 15;
    const int q0 = blockIdx.x * 64;
    const size_t pbase = (size_t)bh * SS * SS;
    const size_t vbase = (size_t)bh * SS * DD;

    float acc[4][4] = {};

    for (int k0 = 0; k0 < SS; k0 += 32) {
        for (int t = tid; t < 512; t += 256) {
            const int r = t >> 3;            // q row 0..63
            const int c = (t & 7) << 2;      // k 0..28
            float4 pv = *(const float4*)(P + pbase + (size_t)(q0 + r) * SS + k0 + c);
            Pst[c + 0][r] = pv.x; Pst[c + 1][r] = pv.y;
            Pst[c + 2][r] = pv.z; Pst[c + 3][r] = pv.w;
        }
        for (int t = tid; t < 512; t += 256) {
            const int r = t >> 4;            // k row 0..31
            const int c = (t & 15) << 2;     // d 0..60
            *(float4*)&Vs[r][c] =
                *(const float4*)(V + vbase + (size_t)(k0 + r) * DD + c);
        }
        __syncthreads();
        #pragma unroll
        for (int kk = 0; kk < 32; kk++) {
            float4 av = *(const float4*)&Pst[kk][ty << 2];
            float4 bv = *(const float4*)&Vs[kk][tx << 2];
            float a[4] = {av.x, av.y, av.z, av.w};
            float bb[4] = {bv.x, bv.y, bv.z, bv.w};
            #pragma unroll
            for (int i = 0; i < 4; i++)
                #pragma unroll
                for (int j = 0; j < 4; j++)
                    acc[i][j] = fmaf(a[i], bb[j], acc[i][j]);
        }
        __syncthreads();
    }

    #pragma unroll
    for (int i = 0; i < 4; i++) {
        const int q = q0 + (ty << 2) + i;
        *(float4*)(Oatt + ((size_t)b * SS + q) * EE + h * DD + (tx << 2)) =
            make_float4(acc[i][0], acc[i][1], acc[i][2], acc[i][3]);
    }
}

// ---------------------------------------------------------------------------
extern "C" void kernel_launch(void* const* d_in, const int* in_sizes, int n_in,
                              void* d_out, int out_size)
{
    const float* query = (const float*)d_in[0];
    const float* key   = (const float*)d_in[1];
    const float* value = (const float*)d_in[2];
    const float* Win   = (const float*)d_in[3];   // [3E, E]
    const float* bin   = (const float*)d_in[4];   // [3E]
    const float* Wout  = (const float*)d_in[5];   // [E, E]
    const float* bout  = (const float*)d_in[6];   // [E]

    float* out  = (float*)d_out;                          // [B,S,E]
    float* wout = out + (size_t)BB * SS * EE;             // [B,S,S]

    float *qp, *kp, *vp, *pp, *ap;
    cudaGetSymbolAddress((void**)&qp, g_q);
    cudaGetSymbolAddress((void**)&kp, g_k);
    cudaGetSymbolAddress((void**)&vp, g_v);
    cudaGetSymbolAddress((void**)&pp, g_p);
    cudaGetSymbolAddress((void**)&ap, g_att);

    dim3 gp(EE / 64, MROWS / 64);
    proj_kernel<<<gp, 256>>>(query, Win,                       bin,          qp, 2);
    proj_kernel<<<gp, 256>>>(key,   Win + (size_t)EE * EE,     bin + EE,     kp, 2);
    proj_kernel<<<gp, 256>>>(value, Win + 2 * (size_t)EE * EE, bin + 2 * EE, vp, 1);

    dim3 gs(SS / 64, SS / 64, BB * HH);
    scores_kernel<<<gs, 256>>>(qp, kp, pp);

    softmax_kernel<<<BB * HH * SS, 256>>>(pp);

    mean_kernel<<<BB * SS, 256>>>(pp, wout);

    dim3 gav(SS / 64, BB * HH);
    av_kernel<<<gav, 256>>>(pp, vp, ap);

    proj_kernel<<<gp, 256>>>(ap, Wout, bout, out, 0);
}

// round 3
// speedup vs baseline: 1.2997x; 1.2997x over previous
#include <cuda_runtime.h>
#include <math.h>
#include <math_constants.h>

#define BB 4
#define SS 2048
#define EE 1024
#define HH 16
#define DD 64
#define MROWS (BB*SS)          // 8192

// -------- device scratch (statically allocated; no cudaMalloc allowed) -----
__device__ float g_q[8388608];          // [B,H,S,D]
__device__ float g_k[8388608];          // [B,H,S,D]
__device__ float g_v[8388608];          // [B,H,S,D]
__device__ float g_att[8388608];        // [B,S,E]  (pre out-proj)
__device__ float g_p[268435456];        // [B,H,S,S] scores / probs (1 GB)

// ---------------------------------------------------------------------------
// proj: C[m,n] = sum_k X[m,k]*W[n,k] + bias[n]
//   mode 0: plain row-major [M,E] output
//   mode 1: head layout [B,H,S,D]
//   mode 2: head layout + RoPE
// 128x128 tile, BK=16, 256 threads, 8x8 microtile.
// ---------------------------------------------------------------------------
__global__ void __launch_bounds__(256)
proj_kernel(const float* __restrict__ X,
            const float* __restrict__ W,
            const float* __restrict__ bias,
            float* __restrict__ out, int mode)
{
    __shared__ float Ast[16][132];
    __shared__ float Wst[16][132];
    const int tid = threadIdx.x;
    const int tx = tid & 15, ty = tid >> 4;
    const int row0 = blockIdx.y * 128;
    const int col0 = blockIdx.x * 128;

    float acc[8][8] = {};

    for (int k0 = 0; k0 < EE; k0 += 16) {
        #pragma unroll
        for (int u = 0; u < 2; u++) {
            const int q = tid + u * 256;          // quad index 0..511
            const int r = q >> 2;                 // row 0..127
            const int kc = (q & 3) << 2;          // 0,4,8,12
            float4 a4 = *(const float4*)(X + (size_t)(row0 + r) * EE + k0 + kc);
            float4 w4 = *(const float4*)(W + (size_t)(col0 + r) * EE + k0 + kc);
            Ast[kc + 0][r] = a4.x; Ast[kc + 1][r] = a4.y;
            Ast[kc + 2][r] = a4.z; Ast[kc + 3][r] = a4.w;
            Wst[kc + 0][r] = w4.x; Wst[kc + 1][r] = w4.y;
            Wst[kc + 2][r] = w4.z; Wst[kc + 3][r] = w4.w;
        }
        __syncthreads();
        #pragma unroll
        for (int k = 0; k < 16; k++) {
            float a[8], b[8];
            *(float4*)(a)     = *(const float4*)&Ast[k][ty * 8];
            *(float4*)(a + 4) = *(const float4*)&Ast[k][ty * 8 + 4];
            *(float4*)(b)     = *(const float4*)&Wst[k][tx * 8];
            *(float4*)(b + 4) = *(const float4*)&Wst[k][tx * 8 + 4];
            #pragma unroll
            for (int i = 0; i < 8; i++)
                #pragma unroll
                for (int j = 0; j < 8; j++)
                    acc[i][j] = fmaf(a[i], b[j], acc[i][j]);
        }
        __syncthreads();
    }

    const int n0 = col0 + tx * 8;
    float bv[8];
    #pragma unroll
    for (int j = 0; j < 8; j++) bv[j] = bias[n0 + j];

    // RoPE inv-freqs depend only on column -> per-thread constants
    float invf[4];
    if (mode == 2) {
        const int d0 = n0 & 63;
        #pragma unroll
        for (int pr = 0; pr < 4; pr++)
            invf[pr] = expf(-(float)((d0 >> 1) + pr) * 0.28782313662425567f);
    }

    const int bidx = row0 / SS;                 // 2048 % 128 == 0: whole tile in one b
    const int h = n0 >> 6, d0 = n0 & 63;

    #pragma unroll
    for (int i = 0; i < 8; i++) {
        const int m = row0 + ty * 8 + i;
        float vals[8];
        #pragma unroll
        for (int j = 0; j < 8; j++) vals[j] = acc[i][j] + bv[j];

        if (mode == 0) {
            *(float4*)(out + (size_t)m * EE + n0)     = make_float4(vals[0], vals[1], vals[2], vals[3]);
            *(float4*)(out + (size_t)m * EE + n0 + 4) = make_float4(vals[4], vals[5], vals[6], vals[7]);
        } else {
            const int spos = m - bidx * SS;
            if (mode == 2) {
                #pragma unroll
                for (int pr = 0; pr < 4; pr++) {
                    const float ang = (float)spos * invf[pr];
                    float sn, cs;
                    sincosf(ang, &sn, &cs);
                    const float v0 = vals[2 * pr], v1 = vals[2 * pr + 1];
                    vals[2 * pr]     = v0 * cs - v1 * sn;
                    vals[2 * pr + 1] = v1 * cs + v0 * sn;
                }
            }
            float* dst = out + (((size_t)(bidx * HH + h) * SS + spos) * DD + d0);
            *(float4*)(dst)     = make_float4(vals[0], vals[1], vals[2], vals[3]);
            *(float4*)(dst + 4) = make_float4(vals[4], vals[5], vals[6], vals[7]);
        }
    }
}

// ---------------------------------------------------------------------------
// scores: P[bh,q,k] = scale * sum_d Q[bh,q,d]*K[bh,k,d]
// 128x128 tile, BK=32 (two chunks of the 64 head dim), 8x8 microtile.
// ---------------------------------------------------------------------------
__global__ void __launch_bounds__(256)
scores_kernel(const float* __restrict__ Q,
              const float* __restrict__ K,
              float* __restrict__ P)
{
    __shared__ float Qst[32][132];   // [d][q]
    __shared__ float Kst[32][132];   // [d][k]
    const int tid = threadIdx.x;
    const int tx = tid & 15, ty = tid >> 4;
    const int bh = blockIdx.z;
    const int q0 = blockIdx.y * 128;
    const int k0 = blockIdx.x * 128;
    const size_t base = (size_t)bh * SS * DD;

    float acc[8][8] = {};

    for (int kc = 0; kc < DD; kc += 32) {
        #pragma unroll
        for (int u = 0; u < 4; u++) {
            const int q = tid + u * 256;        // 1024 quads: 128 rows x 8 quads
            const int r = q >> 3;
            const int c = (q & 7) << 2;
            float4 qv = *(const float4*)(Q + base + (size_t)(q0 + r) * DD + kc + c);
            float4 kv = *(const float4*)(K + base + (size_t)(k0 + r) * DD + kc + c);
            Qst[c + 0][r] = qv.x; Qst[c + 1][r] = qv.y;
            Qst[c + 2][r] = qv.z; Qst[c + 3][r] = qv.w;
            Kst[c + 0][r] = kv.x; Kst[c + 1][r] = kv.y;
            Kst[c + 2][r] = kv.z; Kst[c + 3][r] = kv.w;
        }
        __syncthreads();
        #pragma unroll
        for (int k = 0; k < 32; k++) {
            float a[8], b[8];
            *(float4*)(a)     = *(const float4*)&Qst[k][ty * 8];
            *(float4*)(a + 4) = *(const float4*)&Qst[k][ty * 8 + 4];
            *(float4*)(b)     = *(const float4*)&Kst[k][tx * 8];
            *(float4*)(b + 4) = *(const float4*)&Kst[k][tx * 8 + 4];
            #pragma unroll
            for (int i = 0; i < 8; i++)
                #pragma unroll
                for (int j = 0; j < 8; j++)
                    acc[i][j] = fmaf(a[i], b[j], acc[i][j]);
        }
        __syncthreads();
    }

    const size_t pbase = (size_t)bh * SS * SS;
    #pragma unroll
    for (int i = 0; i < 8; i++) {
        float* dst = P + pbase + (size_t)(q0 + ty * 8 + i) * SS + k0 + tx * 8;
        *(float4*)(dst)     = make_float4(acc[i][0] * 0.125f, acc[i][1] * 0.125f,
                                          acc[i][2] * 0.125f, acc[i][3] * 0.125f);
        *(float4*)(dst + 4) = make_float4(acc[i][4] * 0.125f, acc[i][5] * 0.125f,
                                          acc[i][6] * 0.125f, acc[i][7] * 0.125f);
    }
}

// ---------------------------------------------------------------------------
// fused softmax (in place over last dim, per bh row) + mean over heads.
// One block per (b,q); loops h = 0..15.
// ---------------------------------------------------------------------------
__global__ void __launch_bounds__(256)
softmax_mean_kernel(float* __restrict__ P, float* __restrict__ wout)
{
    const int bq = blockIdx.x;                  // 0 .. B*S-1
    const int b = bq >> 11, q = bq & 2047;
    const int tid = threadIdx.x;
    const int lane = tid & 31, warp = tid >> 5;
    __shared__ float red[8];

    float macc[8] = {};

    for (int h = 0; h < HH; h++) {
        float* p = P + (((size_t)(b * HH + h) * SS + q) * SS);

        float v[8];
        #pragma unroll
        for (int i = 0; i < 8; i++) v[i] = p[tid + (i << 8)];

        float m = v[0];
        #pragma unroll
        for (int i = 1; i < 8; i++) m = fmaxf(m, v[i]);
        #pragma unroll
        for (int o = 16; o; o >>= 1) m = fmaxf(m, __shfl_xor_sync(0xffffffffu, m, o));
        if (lane == 0) red[warp] = m;
        __syncthreads();
        if (tid < 32) {
            float t = (tid < 8) ? red[tid] : -CUDART_INF_F;
            #pragma unroll
            for (int o = 4; o; o >>= 1) t = fmaxf(t, __shfl_xor_sync(0xffffffffu, t, o));
            if (tid == 0) red[0] = t;
        }
        __syncthreads();
        m = red[0];
        __syncthreads();

        float sum = 0.f;
        #pragma unroll
        for (int i = 0; i < 8; i++) { v[i] = expf(v[i] - m); sum += v[i]; }
        #pragma unroll
        for (int o = 16; o; o >>= 1) sum += __shfl_xor_sync(0xffffffffu, sum, o);
        if (lane == 0) red[warp] = sum;
        __syncthreads();
        if (tid < 32) {
            float t = (tid < 8) ? red[tid] : 0.f;
            #pragma unroll
            for (int o = 4; o; o >>= 1) t += __shfl_xor_sync(0xffffffffu, t, o);
            if (tid == 0) red[0] = t;
        }
        __syncthreads();
        const float inv = 1.0f / red[0];
        #pragma unroll
        for (int i = 0; i < 8; i++) {
            v[i] *= inv;
            p[tid + (i << 8)] = v[i];
            macc[i] += v[i];
        }
        __syncthreads();
    }

    float* w = wout + (size_t)bq * SS;
    #pragma unroll
    for (int i = 0; i < 8; i++) w[tid + (i << 8)] = macc[i] * (1.0f / HH);
}

// ---------------------------------------------------------------------------
// attn @ V: Oatt[b,q,h*64+d] = sum_k P[bh,q,k]*V[bh,k,d]
// 128(q) x 64(d) tile, BK=32, 256 threads, 8x4 microtile.
// ---------------------------------------------------------------------------
__global__ void __launch_bounds__(256)
av_kernel(const float* __restrict__ P,
          const float* __restrict__ V,
          float* __restrict__ Oatt)
{
    __shared__ float Pst[32][132];   // [k][q]
    __shared__ float Vs[32][68];     // [k][d]
    const int tid = threadIdx.x;
    const int tx = tid & 15, ty = tid >> 4;
    const int bh = blockIdx.y;
    const int b = bh >> 4, h = bh & 15;
    const int q0 = blockIdx.x * 128;
    const size_t pbase = (size_t)bh * SS * SS;
    const size_t vbase = (size_t)bh * SS * DD;

    float acc[8][4] = {};

    for (int k0 = 0; k0 < SS; k0 += 32) {
        #pragma unroll
        for (int u = 0; u < 4; u++) {
            const int q = tid + u * 256;        // 1024 quads: 128 rows x 8 quads
            const int r = q >> 3;
            const int c = (q & 7) << 2;
            float4 pv = *(const float4*)(P + pbase + (size_t)(q0 + r) * SS + k0 + c);
            Pst[c + 0][r] = pv.x; Pst[c + 1][r] = pv.y;
            Pst[c + 2][r] = pv.z; Pst[c + 3][r] = pv.w;
        }
        #pragma unroll
        for (int u = 0; u < 2; u++) {
            const int q = tid + u * 256;        // 512 quads: 32 rows x 16 quads
            const int r = q >> 4;
            const int c = (q & 15) << 2;
            *(float4*)&Vs[r][c] = *(const float4*)(V + vbase + (size_t)(k0 + r) * DD + c);
        }
        __syncthreads();
        #pragma unroll
        for (int kk = 0; kk < 32; kk++) {
            float a[8], bb[4];
            *(float4*)(a)     = *(const float4*)&Pst[kk][ty * 8];
            *(float4*)(a + 4) = *(const float4*)&Pst[kk][ty * 8 + 4];
            *(float4*)(bb)    = *(const float4*)&Vs[kk][tx * 4];
            #pragma unroll
            for (int i = 0; i < 8; i++)
                #pragma unroll
                for (int j = 0; j < 4; j++)
                    acc[i][j] = fmaf(a[i], bb[j], acc[i][j]);
        }
        __syncthreads();
    }

    #pragma unroll
    for (int i = 0; i < 8; i++) {
        const int q = q0 + ty * 8 + i;
        *(float4*)(Oatt + ((size_t)b * SS + q) * EE + h * DD + tx * 4) =
            make_float4(acc[i][0], acc[i][1], acc[i][2], acc[i][3]);
    }
}

// ---------------------------------------------------------------------------
extern "C" void kernel_launch(void* const* d_in, const int* in_sizes, int n_in,
                              void* d_out, int out_size)
{
    const float* query = (const float*)d_in[0];
    const float* key   = (const float*)d_in[1];
    const float* value = (const float*)d_in[2];
    const float* Win   = (const float*)d_in[3];   // [3E, E]
    const float* bin   = (const float*)d_in[4];   // [3E]
    const float* Wout  = (const float*)d_in[5];   // [E, E]
    const float* bout  = (const float*)d_in[6];   // [E]

    float* out  = (float*)d_out;                          // [B,S,E]
    float* wout = out + (size_t)BB * SS * EE;             // [B,S,S]

    float *qp, *kp, *vp, *pp, *ap;
    cudaGetSymbolAddress((void**)&qp, g_q);
    cudaGetSymbolAddress((void**)&kp, g_k);
    cudaGetSymbolAddress((void**)&vp, g_v);
    cudaGetSymbolAddress((void**)&pp, g_p);
    cudaGetSymbolAddress((void**)&ap, g_att);

    dim3 gp(EE / 128, MROWS / 128);
    proj_kernel<<<gp, 256>>>(query, Win,                       bin,          qp, 2);
    proj_kernel<<<gp, 256>>>(key,   Win + (size_t)EE * EE,     bin + EE,     kp, 2);
    proj_kernel<<<gp, 256>>>(value, Win + 2 * (size_t)EE * EE, bin + 2 * EE, vp, 1);

    dim3 gs(SS / 128, SS / 128, BB * HH);
    scores_kernel<<<gs, 256>>>(qp, kp, pp);

    softmax_mean_kernel<<<BB * SS, 256>>>(pp, wout);

    dim3 gav(SS / 128, BB * HH);
    av_kernel<<<gav, 256>>>(pp, vp, ap);

    proj_kernel<<<gp, 256>>>(ap, Wout, bout, out, 0);
}

// round 4
// speedup vs baseline: 1.3661x; 1.0511x over previous
#include <cuda_runtime.h>
#include <math.h>
#include <math_constants.h>

#define BB 4
#define SS 2048
#define EE 1024
#define HH 16
#define DD 64
#define MROWS (BB*SS)          // 8192

// -------- device scratch (statically allocated; no cudaMalloc allowed) -----
__device__ float g_q[8388608];          // [B,H,S,D]
__device__ float g_k[8388608];          // [B,H,S,D]
__device__ float g_v[8388608];          // [B,H,S,D]
__device__ float g_att[8388608];        // [B,S,E]  (pre out-proj)
__device__ float g_p[268435456];        // [B,H,S,S] scores / probs (1 GB)

// ---------------------------------------------------------------------------
// proj: C[m,n] = sum_k X[m,k]*W[n,k] + bias[n]
//   mode 0: plain row-major [M,E] output
//   mode 1: head layout [B,H,S,D]
//   mode 2: head layout + RoPE
// 128x128 tile, BK=16, 256 threads, 8x8 microtile split into 4x4 quadrants
// (cols tx*4 and tx*4+64, rows ty*4 and ty*4+64) so every compute LDS.128 is
// 16B-stride conflict-free.
// ---------------------------------------------------------------------------
__global__ void __launch_bounds__(256)
proj_kernel(const float* __restrict__ X,
            const float* __restrict__ W,
            const float* __restrict__ bias,
            float* __restrict__ out, int mode)
{
    __shared__ float Ast[16][132];
    __shared__ float Wst[16][132];
    const int tid = threadIdx.x;
    const int tx = tid & 15, ty = tid >> 4;
    const int row0 = blockIdx.y * 128;
    const int col0 = blockIdx.x * 128;

    float acc[8][8] = {};

    for (int k0 = 0; k0 < EE; k0 += 16) {
        #pragma unroll
        for (int u = 0; u < 2; u++) {
            const int q = tid + u * 256;          // quad index 0..511
            const int r = q >> 2;                 // row 0..127
            const int kc = (q & 3) << 2;          // 0,4,8,12
            float4 a4 = *(const float4*)(X + (size_t)(row0 + r) * EE + k0 + kc);
            float4 w4 = *(const float4*)(W + (size_t)(col0 + r) * EE + k0 + kc);
            Ast[kc + 0][r] = a4.x; Ast[kc + 1][r] = a4.y;
            Ast[kc + 2][r] = a4.z; Ast[kc + 3][r] = a4.w;
            Wst[kc + 0][r] = w4.x; Wst[kc + 1][r] = w4.y;
            Wst[kc + 2][r] = w4.z; Wst[kc + 3][r] = w4.w;
        }
        __syncthreads();
        #pragma unroll
        for (int k = 0; k < 16; k++) {
            float a[8], b[8];
            *(float4*)(a)     = *(const float4*)&Ast[k][ty * 4];
            *(float4*)(a + 4) = *(const float4*)&Ast[k][ty * 4 + 64];
            *(float4*)(b)     = *(const float4*)&Wst[k][tx * 4];
            *(float4*)(b + 4) = *(const float4*)&Wst[k][tx * 4 + 64];
            #pragma unroll
            for (int i = 0; i < 8; i++)
                #pragma unroll
                for (int j = 0; j < 8; j++)
                    acc[i][j] = fmaf(a[i], b[j], acc[i][j]);
        }
        __syncthreads();
    }

    const int n0a = col0 + tx * 4;        // first col group
    const int n0b = n0a + 64;             // second col group (next head, same d0)
    float bv[8];
    #pragma unroll
    for (int j = 0; j < 4; j++) { bv[j] = bias[n0a + j]; bv[j + 4] = bias[n0b + j]; }

    // RoPE inv-freqs: d0 = tx*4 for BOTH col groups (they differ by a whole head)
    float invf[2];
    if (mode == 2) {
        #pragma unroll
        for (int pr = 0; pr < 2; pr++)
            invf[pr] = expf(-(float)(tx * 2 + pr) * 0.28782313662425567f);
    }

    const int bidx = row0 / SS;           // 2048 % 128 == 0: whole tile in one b
    const int ha = n0a >> 6;              // head of col group a; group b is ha+1
    const int d0 = tx * 4;

    #pragma unroll
    for (int i = 0; i < 8; i++) {
        const int m = row0 + ty * 4 + ((i < 4) ? i : (60 + i));   // +64 for 2nd quad
        float vals[8];
        #pragma unroll
        for (int j = 0; j < 8; j++) vals[j] = acc[i][j] + bv[j];

        if (mode == 0) {
            *(float4*)(out + (size_t)m * EE + n0a) = make_float4(vals[0], vals[1], vals[2], vals[3]);
            *(float4*)(out + (size_t)m * EE + n0b) = make_float4(vals[4], vals[5], vals[6], vals[7]);
        } else {
            const int spos = m - bidx * SS;
            if (mode == 2) {
                #pragma unroll
                for (int g = 0; g < 2; g++) {
                    #pragma unroll
                    for (int pr = 0; pr < 2; pr++) {
                        const float ang = (float)spos * invf[pr];
                        float sn, cs;
                        sincosf(ang, &sn, &cs);
                        const int e = g * 4 + 2 * pr;
                        const float v0 = vals[e], v1 = vals[e + 1];
                        vals[e]     = v0 * cs - v1 * sn;
                        vals[e + 1] = v1 * cs + v0 * sn;
                    }
                }
            }
            float* dstA = out + (((size_t)(bidx * HH + ha) * SS + spos) * DD + d0);
            float* dstB = out + (((size_t)(bidx * HH + ha + 1) * SS + spos) * DD + d0);
            *(float4*)(dstA) = make_float4(vals[0], vals[1], vals[2], vals[3]);
            *(float4*)(dstB) = make_float4(vals[4], vals[5], vals[6], vals[7]);
        }
    }
}

// ---------------------------------------------------------------------------
// scores: P[bh,q,k] = scale * sum_d Q[bh,q,d]*K[bh,k,d]
// 128x128 tile, BK=32, 8x8 microtile in 4x4 quadrants (conflict-free LDS).
// ---------------------------------------------------------------------------
__global__ void __launch_bounds__(256)
scores_kernel(const float* __restrict__ Q,
              const float* __restrict__ K,
              float* __restrict__ P)
{
    __shared__ float Qst[32][132];   // [d][q]
    __shared__ float Kst[32][132];   // [d][k]
    const int tid = threadIdx.x;
    const int tx = tid & 15, ty = tid >> 4;
    const int bh = blockIdx.z;
    const int q0 = blockIdx.y * 128;
    const int k0 = blockIdx.x * 128;
    const size_t base = (size_t)bh * SS * DD;

    float acc[8][8] = {};

    for (int kc = 0; kc < DD; kc += 32) {
        #pragma unroll
        for (int u = 0; u < 4; u++) {
            const int q = tid + u * 256;        // 1024 quads: 128 rows x 8 quads
            const int r = q >> 3;
            const int c = (q & 7) << 2;
            float4 qv = *(const float4*)(Q + base + (size_t)(q0 + r) * DD + kc + c);
            float4 kv = *(const float4*)(K + base + (size_t)(k0 + r) * DD + kc + c);
            Qst[c + 0][r] = qv.x; Qst[c + 1][r] = qv.y;
            Qst[c + 2][r] = qv.z; Qst[c + 3][r] = qv.w;
            Kst[c + 0][r] = kv.x; Kst[c + 1][r] = kv.y;
            Kst[c + 2][r] = kv.z; Kst[c + 3][r] = kv.w;
        }
        __syncthreads();
        #pragma unroll
        for (int k = 0; k < 32; k++) {
            float a[8], b[8];
            *(float4*)(a)     = *(const float4*)&Qst[k][ty * 4];
            *(float4*)(a + 4) = *(const float4*)&Qst[k][ty * 4 + 64];
            *(float4*)(b)     = *(const float4*)&Kst[k][tx * 4];
            *(float4*)(b + 4) = *(const float4*)&Kst[k][tx * 4 + 64];
            #pragma unroll
            for (int i = 0; i < 8; i++)
                #pragma unroll
                for (int j = 0; j < 8; j++)
                    acc[i][j] = fmaf(a[i], b[j], acc[i][j]);
        }
        __syncthreads();
    }

    const size_t pbase = (size_t)bh * SS * SS;
    #pragma unroll
    for (int i = 0; i < 8; i++) {
        const int qr = q0 + ty * 4 + ((i < 4) ? i : (60 + i));
        float* dst = P + pbase + (size_t)qr * SS + k0 + tx * 4;
        *(float4*)(dst)      = make_float4(acc[i][0] * 0.125f, acc[i][1] * 0.125f,
                                           acc[i][2] * 0.125f, acc[i][3] * 0.125f);
        *(float4*)(dst + 64) = make_float4(acc[i][4] * 0.125f, acc[i][5] * 0.125f,
                                           acc[i][6] * 0.125f, acc[i][7] * 0.125f);
    }
}

// ---------------------------------------------------------------------------
// fused softmax (in place over last dim, per bh row) + mean over heads.
// One block per (b,q); loops h = 0..15.
// ---------------------------------------------------------------------------
__global__ void __launch_bounds__(256)
softmax_mean_kernel(float* __restrict__ P, float* __restrict__ wout)
{
    const int bq = blockIdx.x;                  // 0 .. B*S-1
    const int b = bq >> 11, q = bq & 2047;
    const int tid = threadIdx.x;
    const int lane = tid & 31, warp = tid >> 5;
    __shared__ float red[8];

    float macc[8] = {};

    for (int h = 0; h < HH; h++) {
        float* p = P + (((size_t)(b * HH + h) * SS + q) * SS);

        float v[8];
        #pragma unroll
        for (int i = 0; i < 8; i++) v[i] = p[tid + (i << 8)];

        float m = v[0];
        #pragma unroll
        for (int i = 1; i < 8; i++) m = fmaxf(m, v[i]);
        #pragma unroll
        for (int o = 16; o; o >>= 1) m = fmaxf(m, __shfl_xor_sync(0xffffffffu, m, o));
        if (lane == 0) red[warp] = m;
        __syncthreads();
        if (tid < 32) {
            float t = (tid < 8) ? red[tid] : -CUDART_INF_F;
            #pragma unroll
            for (int o = 4; o; o >>= 1) t = fmaxf(t, __shfl_xor_sync(0xffffffffu, t, o));
            if (tid == 0) red[0] = t;
        }
        __syncthreads();
        m = red[0];
        __syncthreads();

        float sum = 0.f;
        #pragma unroll
        for (int i = 0; i < 8; i++) { v[i] = expf(v[i] - m); sum += v[i]; }
        #pragma unroll
        for (int o = 16; o; o >>= 1) sum += __shfl_xor_sync(0xffffffffu, sum, o);
        if (lane == 0) red[warp] = sum;
        __syncthreads();
        if (tid < 32) {
            float t = (tid < 8) ? red[tid] : 0.f;
            #pragma unroll
            for (int o = 4; o; o >>= 1) t += __shfl_xor_sync(0xffffffffu, t, o);
            if (tid == 0) red[0] = t;
        }
        __syncthreads();
        const float inv = 1.0f / red[0];
        #pragma unroll
        for (int i = 0; i < 8; i++) {
            v[i] *= inv;
            p[tid + (i << 8)] = v[i];
            macc[i] += v[i];
        }
        __syncthreads();
    }

    float* w = wout + (size_t)bq * SS;
    #pragma unroll
    for (int i = 0; i < 8; i++) w[tid + (i << 8)] = macc[i] * (1.0f / HH);
}

// ---------------------------------------------------------------------------
// attn @ V: Oatt[b,q,h*64+d] = sum_k P[bh,q,k]*V[bh,k,d]
// 128(q) x 64(d) tile, BK=32, 256 threads, 8x4 microtile (already
// conflict-free: a-loads broadcast, b-loads 16B stride).
// ---------------------------------------------------------------------------
__global__ void __launch_bounds__(256)
av_kernel(const float* __restrict__ P,
          const float* __restrict__ V,
          float* __restrict__ Oatt)
{
    __shared__ float Pst[32][132];   // [k][q]
    __shared__ float Vs[32][68];     // [k][d]
    const int tid = threadIdx.x;
    const int tx = tid & 15, ty = tid >> 4;
    const int bh = blockIdx.y;
    const int b = bh >> 4, h = bh & 15;
    const int q0 = blockIdx.x * 128;
    const size_t pbase = (size_t)bh * SS * SS;
    const size_t vbase = (size_t)bh * SS * DD;

    float acc[8][4] = {};

    for (int k0 = 0; k0 < SS; k0 += 32) {
        #pragma unroll
        for (int u = 0; u < 4; u++) {
            const int q = tid + u * 256;        // 1024 quads: 128 rows x 8 quads
            const int r = q >> 3;
            const int c = (q & 7) << 2;
            float4 pv = *(const float4*)(P + pbase + (size_t)(q0 + r) * SS + k0 + c);
            Pst[c + 0][r] = pv.x; Pst[c + 1][r] = pv.y;
            Pst[c + 2][r] = pv.z; Pst[c + 3][r] = pv.w;
        }
        #pragma unroll
        for (int u = 0; u < 2; u++) {
            const int q = tid + u * 256;        // 512 quads: 32 rows x 16 quads
            const int r = q >> 4;
            const int c = (q & 15) << 2;
            *(float4*)&Vs[r][c] = *(const float4*)(V + vbase + (size_t)(k0 + r) * DD + c);
        }
        __syncthreads();
        #pragma unroll
        for (int kk = 0; kk < 32; kk++) {
            float a[8], bb[4];
            *(float4*)(a)     = *(const float4*)&Pst[kk][ty * 4];
            *(float4*)(a + 4) = *(const float4*)&Pst[kk][ty * 4 + 64];
            *(float4*)(bb)    = *(const float4*)&Vs[kk][tx * 4];
            #pragma unroll
            for (int i = 0; i < 8; i++)
                #pragma unroll
                for (int j = 0; j < 4; j++)
                    acc[i][j] = fmaf(a[i], bb[j], acc[i][j]);
        }
        __syncthreads();
    }

    #pragma unroll
    for (int i = 0; i < 8; i++) {
        const int q = q0 + ty * 4 + ((i < 4) ? i : (60 + i));
        *(float4*)(Oatt + ((size_t)b * SS + q) * EE + h * DD + tx * 4) =
            make_float4(acc[i][0], acc[i][1], acc[i][2], acc[i][3]);
    }
}

// ---------------------------------------------------------------------------
extern "C" void kernel_launch(void* const* d_in, const int* in_sizes, int n_in,
                              void* d_out, int out_size)
{
    const float* query = (const float*)d_in[0];
    const float* key   = (const float*)d_in[1];
    const float* value = (const float*)d_in[2];
    const float* Win   = (const float*)d_in[3];   // [3E, E]
    const float* bin   = (const float*)d_in[4];   // [3E]
    const float* Wout  = (const float*)d_in[5];   // [E, E]
    const float* bout  = (const float*)d_in[6];   // [E]

    float* out  = (float*)d_out;                          // [B,S,E]
    float* wout = out + (size_t)BB * SS * EE;             // [B,S,S]

    float *qp, *kp, *vp, *pp, *ap;
    cudaGetSymbolAddress((void**)&qp, g_q);
    cudaGetSymbolAddress((void**)&kp, g_k);
    cudaGetSymbolAddress((void**)&vp, g_v);
    cudaGetSymbolAddress((void**)&pp, g_p);
    cudaGetSymbolAddress((void**)&ap, g_att);

    dim3 gp(EE / 128, MROWS / 128);
    proj_kernel<<<gp, 256>>>(query, Win,                       bin,          qp, 2);
    proj_kernel<<<gp, 256>>>(key,   Win + (size_t)EE * EE,     bin + EE,     kp, 2);
    proj_kernel<<<gp, 256>>>(value, Win + 2 * (size_t)EE * EE, bin + 2 * EE, vp, 1);

    dim3 gs(SS / 128, SS / 128, BB * HH);
    scores_kernel<<<gs, 256>>>(qp, kp, pp);

    softmax_mean_kernel<<<BB * SS, 256>>>(pp, wout);

    dim3 gav(SS / 128, BB * HH);
    av_kernel<<<gav, 256>>>(pp, vp, ap);

    proj_kernel<<<gp, 256>>>(ap, Wout, bout, out, 0);
}

// round 6
// speedup vs baseline: 1.7407x; 1.2742x over previous
#include <cuda_runtime.h>
#include <cuda_bf16.h>
#include <math.h>
#include <math_constants.h>
#include <cstdint>

#define BB 4
#define SS 2048
#define EE 1024
#define HH 16
#define DD 64
#define MROWS (BB*SS)          // 8192

// -------- device scratch (statically allocated; no cudaMalloc allowed) -----
__device__ float g_q[8388608];          // [B,H,S,D] fp32
__device__ float g_k[8388608];          // [B,H,S,D] fp32
__device__ float g_v[8388608];          // [B,H,S,D] fp32
__device__ float g_att[8388608];        // [B,S,E]  (pre out-proj)
__device__ float g_p[268435456];        // [B,H,S,S] scores / probs (1 GB)

// bf16 split planes
__device__ __nv_bfloat16 g_xqh[8388608], g_xql[8388608];
__device__ __nv_bfloat16 g_xkh[8388608], g_xkl[8388608];
__device__ __nv_bfloat16 g_xvh[8388608], g_xvl[8388608];
__device__ __nv_bfloat16 g_wh[3145728],  g_wl[3145728];    // in_proj W [3E,E]
__device__ __nv_bfloat16 g_woh[1048576], g_wol[1048576];   // out_proj W [E,E]
__device__ __nv_bfloat16 g_ah[8388608],  g_al[8388608];    // att split

// ============================ PTX helpers ==================================
__device__ __forceinline__ uint32_t smem_u32(const void* p) {
    uint32_t a;
    asm("{ .reg .u64 t; cvta.to.shared.u64 t, %1; cvt.u32.u64 %0, t; }"
        : "=r"(a) : "l"(p));
    return a;
}
__device__ __forceinline__ void ldsm_x4(uint32_t* r, uint32_t addr) {
    asm volatile("ldmatrix.sync.aligned.m8n8.x4.shared.b16 {%0,%1,%2,%3}, [%4];"
        : "=r"(r[0]), "=r"(r[1]), "=r"(r[2]), "=r"(r[3]) : "r"(addr));
}
__device__ __forceinline__ void mma_bf16(float* d, const uint32_t* a, const uint32_t* b) {
    asm volatile("mma.sync.aligned.m16n8k16.row.col.f32.bf16.bf16.f32 "
        "{%0,%1,%2,%3}, {%4,%5,%6,%7}, {%8,%9}, {%0,%1,%2,%3};"
        : "+f"(d[0]), "+f"(d[1]), "+f"(d[2]), "+f"(d[3])
        : "r"(a[0]), "r"(a[1]), "r"(a[2]), "r"(a[3]), "r"(b[0]), "r"(b[1]));
}

// ============================ split kernel =================================
__global__ void __launch_bounds__(256)
split_kernel(const float* __restrict__ src,
             __nv_bfloat16* __restrict__ hi,
             __nv_bfloat16* __restrict__ lo, int n4)
{
    int i = blockIdx.x * 256 + threadIdx.x;
    if (i >= n4) return;
    float4 x = ((const float4*)src)[i];
    __nv_bfloat16 h0 = __float2bfloat16_rn(x.x);
    __nv_bfloat16 h1 = __float2bfloat16_rn(x.y);
    __nv_bfloat16 h2 = __float2bfloat16_rn(x.z);
    __nv_bfloat16 h3 = __float2bfloat16_rn(x.w);
    __nv_bfloat16 l0 = __float2bfloat16_rn(x.x - __bfloat162float(h0));
    __nv_bfloat16 l1 = __float2bfloat16_rn(x.y - __bfloat162float(h1));
    __nv_bfloat16 l2 = __float2bfloat16_rn(x.z - __bfloat162float(h2));
    __nv_bfloat16 l3 = __float2bfloat16_rn(x.w - __bfloat162float(h3));
    uint2 hv, lv;
    hv.x = (uint32_t)__bfloat16_as_ushort(h0) | ((uint32_t)__bfloat16_as_ushort(h1) << 16);
    hv.y = (uint32_t)__bfloat16_as_ushort(h2) | ((uint32_t)__bfloat16_as_ushort(h3) << 16);
    lv.x = (uint32_t)__bfloat16_as_ushort(l0) | ((uint32_t)__bfloat16_as_ushort(l1) << 16);
    lv.y = (uint32_t)__bfloat16_as_ushort(l2) | ((uint32_t)__bfloat16_as_ushort(l3) << 16);
    *(uint2*)(hi + (size_t)i * 4) = hv;
    *(uint2*)(lo + (size_t)i * 4) = lv;
}

// ============================ HMMA GEMM ====================================
// C[m,n] = sum_k A[m,k]*B[n,k] + bias[n], split bf16, fp32 accum via
// mma.sync m16n8k16.  Block tile 128x128, 8 warps (2 m x 4 n), warp 64x32.
// mode 0: row-major [M,1024] ; mode 1: [B,H,S,D] scatter ; mode 2: +RoPE
#define LDA 40   // smem row stride in halves (80B -> conflict-free LDSM)

__global__ void __launch_bounds__(256)
gemm_split_kernel(const __nv_bfloat16* __restrict__ Ah_,
                  const __nv_bfloat16* __restrict__ Al_,
                  const __nv_bfloat16* __restrict__ Bh_,
                  const __nv_bfloat16* __restrict__ Bl_,
                  const float* __restrict__ bias,
                  float* __restrict__ dst, int mode)
{
    __shared__ __nv_bfloat16 sAh[128 * LDA], sAl[128 * LDA];
    __shared__ __nv_bfloat16 sBh[128 * LDA], sBl[128 * LDA];
    const int tid = threadIdx.x;
    const int w = tid >> 5, lane = tid & 31;
    const int wm = w & 1, wn = w >> 1;           // m off = wm*64, n off = wn*32
    const int row0 = blockIdx.y * 128, col0 = blockIdx.x * 128;

    float acc[4][4][4] = {};

    // ldmatrix per-thread address components (in halves)
    const int a_r = lane & 15;                   // row within 16
    const int a_c = (lane >> 4) << 3;            // col 0 or 8
    const int b_n = (lane & 7) + ((lane >> 4) & 1) * 8;
    const int b_k = ((lane >> 3) & 1) * 8;

    const int ld_r  = tid >> 2;                  // 0..63 (stage-load row, 2 iters)
    const int ld_c8 = (tid & 3) << 3;            // 0,8,16,24

    for (int k0 = 0; k0 < EE; k0 += 32) {
        #pragma unroll
        for (int u = 0; u < 2; u++) {
            const int r = ld_r + u * 64;
            const size_t ga = (size_t)(row0 + r) * EE + k0 + ld_c8;
            const size_t gb = (size_t)(col0 + r) * EE + k0 + ld_c8;
            *(uint4*)&sAh[r * LDA + ld_c8] = *(const uint4*)(Ah_ + ga);
            *(uint4*)&sAl[r * LDA + ld_c8] = *(const uint4*)(Al_ + ga);
            *(uint4*)&sBh[r * LDA + ld_c8] = *(const uint4*)(Bh_ + gb);
            *(uint4*)&sBl[r * LDA + ld_c8] = *(const uint4*)(Bl_ + gb);
        }
        __syncthreads();
        #pragma unroll
        for (int ks = 0; ks < 32; ks += 16) {
            uint32_t bfh[4][2], bfl[4][2];
            #pragma unroll
            for (int pr = 0; pr < 2; pr++) {
                const int nrow = wn * 32 + pr * 16 + b_n;
                uint32_t t[4];
                ldsm_x4(t, smem_u32(&sBh[nrow * LDA + ks + b_k]));
                bfh[2*pr][0] = t[0]; bfh[2*pr][1] = t[1];
                bfh[2*pr+1][0] = t[2]; bfh[2*pr+1][1] = t[3];
                ldsm_x4(t, smem_u32(&sBl[nrow * LDA + ks + b_k]));
                bfl[2*pr][0] = t[0]; bfl[2*pr][1] = t[1];
                bfl[2*pr+1][0] = t[2]; bfl[2*pr+1][1] = t[3];
            }
            uint32_t af[4][4];
            #pragma unroll
            for (int mt = 0; mt < 4; mt++)
                ldsm_x4(af[mt], smem_u32(&sAh[(wm*64 + mt*16 + a_r) * LDA + ks + a_c]));
            #pragma unroll
            for (int mt = 0; mt < 4; mt++)
                #pragma unroll
                for (int nt = 0; nt < 4; nt++) {
                    mma_bf16(acc[mt][nt], af[mt], bfh[nt]);
                    mma_bf16(acc[mt][nt], af[mt], bfl[nt]);
                }
            #pragma unroll
            for (int mt = 0; mt < 4; mt++)
                ldsm_x4(af[mt], smem_u32(&sAl[(wm*64 + mt*16 + a_r) * LDA + ks + a_c]));
            #pragma unroll
            for (int mt = 0; mt < 4; mt++)
                #pragma unroll
                for (int nt = 0; nt < 4; nt++)
                    mma_bf16(acc[mt][nt], af[mt], bfh[nt]);
        }
        __syncthreads();
    }

    // ---------------- epilogue: acc -> global (bias / RoPE / scatter) ------
    const int r4 = lane >> 2, c2 = (lane & 3) << 1;

    // per-nt column bases + bias + RoPE inv freq (cols fixed per thread)
    float bs0[4], bs1[4], invs[4];
    #pragma unroll
    for (int nt = 0; nt < 4; nt++) {
        const int col = col0 + wn * 32 + nt * 8 + c2;
        bs0[nt] = bias[col];
        bs1[nt] = bias[col + 1];
        invs[nt] = expf(-(float)((col & 63) >> 1) * 0.28782313662425567f);
    }

    #pragma unroll
    for (int mt = 0; mt < 4; mt++) {
        #pragma unroll
        for (int rh = 0; rh < 2; rh++) {
            const int m = row0 + wm * 64 + mt * 16 + rh * 8 + r4;
            const int b = m >> 11, s = m & 2047;
            #pragma unroll
            for (int nt = 0; nt < 4; nt++) {
                const int col = col0 + wn * 32 + nt * 8 + c2;
                float v0 = acc[mt][nt][rh * 2 + 0] + bs0[nt];
                float v1 = acc[mt][nt][rh * 2 + 1] + bs1[nt];
                if (mode == 0) {
                    *(float2*)(dst + (size_t)m * EE + col) = make_float2(v0, v1);
                } else {
                    if (mode == 2) {
                        float sn, cs;
                        sincosf((float)s * invs[nt], &sn, &cs);
                        const float t0 = v0, t1 = v1;
                        v0 = t0 * cs - t1 * sn;
                        v1 = t1 * cs + t0 * sn;
                    }
                    const int h = col >> 6, d0 = col & 63;
                    *(float2*)(dst + (((size_t)(b * HH + h) * SS + s) * DD + d0)) =
                        make_float2(v0, v1);
                }
            }
        }
    }
}

// ---------------------------------------------------------------------------
// scores: P[bh,q,k] = scale * sum_d Q[bh,q,d]*K[bh,k,d]   (SIMT fp32)
// ---------------------------------------------------------------------------
__global__ void __launch_bounds__(256)
scores_kernel(const float* __restrict__ Q,
              const float* __restrict__ K,
              float* __restrict__ P)
{
    __shared__ float Qst[32][132];
    __shared__ float Kst[32][132];
    const int tid = threadIdx.x;
    const int tx = tid & 15, ty = tid >> 4;
    const int bh = blockIdx.z;
    const int q0 = blockIdx.y * 128;
    const int k0 = blockIdx.x * 128;
    const size_t base = (size_t)bh * SS * DD;

    float acc[8][8] = {};

    for (int kc = 0; kc < DD; kc += 32) {
        #pragma unroll
        for (int u = 0; u < 4; u++) {
            const int q = tid + u * 256;
            const int r = q >> 3;
            const int c = (q & 7) << 2;
            float4 qv = *(const float4*)(Q + base + (size_t)(q0 + r) * DD + kc + c);
            float4 kv = *(const float4*)(K + base + (size_t)(k0 + r) * DD + kc + c);
            Qst[c + 0][r] = qv.x; Qst[c + 1][r] = qv.y;
            Qst[c + 2][r] = qv.z; Qst[c + 3][r] = qv.w;
            Kst[c + 0][r] = kv.x; Kst[c + 1][r] = kv.y;
            Kst[c + 2][r] = kv.z; Kst[c + 3][r] = kv.w;
        }
        __syncthreads();
        #pragma unroll
        for (int k = 0; k < 32; k++) {
            float a[8], b[8];
            *(float4*)(a)     = *(const float4*)&Qst[k][ty * 4];
            *(float4*)(a + 4) = *(const float4*)&Qst[k][ty * 4 + 64];
            *(float4*)(b)     = *(const float4*)&Kst[k][tx * 4];
            *(float4*)(b + 4) = *(const float4*)&Kst[k][tx * 4 + 64];
            #pragma unroll
            for (int i = 0; i < 8; i++)
                #pragma unroll
                for (int j = 0; j < 8; j++)
                    acc[i][j] = fmaf(a[i], b[j], acc[i][j]);
        }
        __syncthreads();
    }

    const size_t pbase = (size_t)bh * SS * SS;
    #pragma unroll
    for (int i = 0; i < 8; i++) {
        const int qr = q0 + ty * 4 + ((i < 4) ? i : (60 + i));
        float* dst = P + pbase + (size_t)qr * SS + k0 + tx * 4;
        *(float4*)(dst)      = make_float4(acc[i][0] * 0.125f, acc[i][1] * 0.125f,
                                           acc[i][2] * 0.125f, acc[i][3] * 0.125f);
        *(float4*)(dst + 64) = make_float4(acc[i][4] * 0.125f, acc[i][5] * 0.125f,
                                           acc[i][6] * 0.125f, acc[i][7] * 0.125f);
    }
}

// ---------------------------------------------------------------------------
// fused softmax + head-mean
// ---------------------------------------------------------------------------
__global__ void __launch_bounds__(256)
softmax_mean_kernel(float* __restrict__ P, float* __restrict__ wout)
{
    const int bq = blockIdx.x;
    const int b = bq >> 11, q = bq & 2047;
    const int tid = threadIdx.x;
    const int lane = tid & 31, warp = tid >> 5;
    __shared__ float red[8];

    float macc[8] = {};

    for (int h = 0; h < HH; h++) {
        float* p = P + (((size_t)(b * HH + h) * SS + q) * SS);

        float v[8];
        #pragma unroll
        for (int i = 0; i < 8; i++) v[i] = p[tid + (i << 8)];

        float m = v[0];
        #pragma unroll
        for (int i = 1; i < 8; i++) m = fmaxf(m, v[i]);
        #pragma unroll
        for (int o = 16; o; o >>= 1) m = fmaxf(m, __shfl_xor_sync(0xffffffffu, m, o));
        if (lane == 0) red[warp] = m;
        __syncthreads();
        if (tid < 32) {
            float t = (tid < 8) ? red[tid] : -CUDART_INF_F;
            #pragma unroll
            for (int o = 4; o; o >>= 1) t = fmaxf(t, __shfl_xor_sync(0xffffffffu, t, o));
            if (tid == 0) red[0] = t;
        }
        __syncthreads();
        m = red[0];
        __syncthreads();

        float sum = 0.f;
        #pragma unroll
        for (int i = 0; i < 8; i++) { v[i] = expf(v[i] - m); sum += v[i]; }
        #pragma unroll
        for (int o = 16; o; o >>= 1) sum += __shfl_xor_sync(0xffffffffu, sum, o);
        if (lane == 0) red[warp] = sum;
        __syncthreads();
        if (tid < 32) {
            float t = (tid < 8) ? red[tid] : 0.f;
            #pragma unroll
            for (int o = 4; o; o >>= 1) t += __shfl_xor_sync(0xffffffffu, t, o);
            if (tid == 0) red[0] = t;
        }
        __syncthreads();
        const float inv = 1.0f / red[0];
        #pragma unroll
        for (int i = 0; i < 8; i++) {
            v[i] *= inv;
            p[tid + (i << 8)] = v[i];
            macc[i] += v[i];
        }
        __syncthreads();
    }

    float* w = wout + (size_t)bq * SS;
    #pragma unroll
    for (int i = 0; i < 8; i++) w[tid + (i << 8)] = macc[i] * (1.0f / HH);
}

// ---------------------------------------------------------------------------
// attn @ V (SIMT fp32)
// ---------------------------------------------------------------------------
__global__ void __launch_bounds__(256)
av_kernel(const float* __restrict__ P,
          const float* __restrict__ V,
          float* __restrict__ Oatt)
{
    __shared__ float Pst[32][132];
    __shared__ float Vs[32][68];
    const int tid = threadIdx.x;
    const int tx = tid & 15, ty = tid >> 4;
    const int bh = blockIdx.y;
    const int b = bh >> 4, h = bh & 15;
    const int q0 = blockIdx.x * 128;
    const size_t pbase = (size_t)bh * SS * SS;
    const size_t vbase = (size_t)bh * SS * DD;

    float acc[8][4] = {};

    for (int k0 = 0; k0 < SS; k0 += 32) {
        #pragma unroll
        for (int u = 0; u < 4; u++) {
            const int q = tid + u * 256;
            const int r = q >> 3;
            const int c = (q & 7) << 2;
            float4 pv = *(const float4*)(P + pbase + (size_t)(q0 + r) * SS + k0 + c);
            Pst[c + 0][r] = pv.x; Pst[c + 1][r] = pv.y;
            Pst[c + 2][r] = pv.z; Pst[c + 3][r] = pv.w;
        }
        #pragma unroll
        for (int u = 0; u < 2; u++) {
            const int q = tid + u * 256;
            const int r = q >> 4;
            const int c = (q & 15) << 2;
            *(float4*)&Vs[r][c] = *(const float4*)(V + vbase + (size_t)(k0 + r) * DD + c);
        }
        __syncthreads();
        #pragma unroll
        for (int kk = 0; kk < 32; kk++) {
            float a[8], bb[4];
            *(float4*)(a)     = *(const float4*)&Pst[kk][ty * 4];
            *(float4*)(a + 4) = *(const float4*)&Pst[kk][ty * 4 + 64];
            *(float4*)(bb)    = *(const float4*)&Vs[kk][tx * 4];
            #pragma unroll
            for (int i = 0; i < 8; i++)
                #pragma unroll
                for (int j = 0; j < 4; j++)
                    acc[i][j] = fmaf(a[i], bb[j], acc[i][j]);
        }
        __syncthreads();
    }

    #pragma unroll
    for (int i = 0; i < 8; i++) {
        const int q = q0 + ty * 4 + ((i < 4) ? i : (60 + i));
        *(float4*)(Oatt + ((size_t)b * SS + q) * EE + h * DD + tx * 4) =
            make_float4(acc[i][0], acc[i][1], acc[i][2], acc[i][3]);
    }
}

// ---------------------------------------------------------------------------
extern "C" void kernel_launch(void* const* d_in, const int* in_sizes, int n_in,
                              void* d_out, int out_size)
{
    const float* query = (const float*)d_in[0];
    const float* key   = (const float*)d_in[1];
    const float* value = (const float*)d_in[2];
    const float* Win   = (const float*)d_in[3];   // [3E, E]
    const float* bin   = (const float*)d_in[4];   // [3E]
    const float* Wout  = (const float*)d_in[5];   // [E, E]
    const float* bout  = (const float*)d_in[6];   // [E]

    float* out  = (float*)d_out;                          // [B,S,E]
    float* wout = out + (size_t)BB * SS * EE;             // [B,S,S]

    float *qp, *kp, *vp, *pp, *ap;
    cudaGetSymbolAddress((void**)&qp, g_q);
    cudaGetSymbolAddress((void**)&kp, g_k);
    cudaGetSymbolAddress((void**)&vp, g_v);
    cudaGetSymbolAddress((void**)&pp, g_p);
    cudaGetSymbolAddress((void**)&ap, g_att);

    __nv_bfloat16 *xqh, *xql, *xkh, *xkl, *xvh, *xvl, *wh, *wl, *woh, *wol, *ah, *al;
    cudaGetSymbolAddress((void**)&xqh, g_xqh);
    cudaGetSymbolAddress((void**)&xql, g_xql);
    cudaGetSymbolAddress((void**)&xkh, g_xkh);
    cudaGetSymbolAddress((void**)&xkl, g_xkl);
    cudaGetSymbolAddress((void**)&xvh, g_xvh);
    cudaGetSymbolAddress((void**)&xvl, g_xvl);
    cudaGetSymbolAddress((void**)&wh,  g_wh);
    cudaGetSymbolAddress((void**)&wl,  g_wl);
    cudaGetSymbolAddress((void**)&woh, g_woh);
    cudaGetSymbolAddress((void**)&wol, g_wol);
    cudaGetSymbolAddress((void**)&ah,  g_ah);
    cudaGetSymbolAddress((void**)&al,  g_al);

    // splits
    split_kernel<<<(MROWS * EE / 4 + 255) / 256, 256>>>(query, xqh, xql, MROWS * EE / 4);
    split_kernel<<<(MROWS * EE / 4 + 255) / 256, 256>>>(key,   xkh, xkl, MROWS * EE / 4);
    split_kernel<<<(MROWS * EE / 4 + 255) / 256, 256>>>(value, xvh, xvl, MROWS * EE / 4);
    split_kernel<<<(3 * EE * EE / 4 + 255) / 256, 256>>>(Win,  wh,  wl,  3 * EE * EE / 4);
    split_kernel<<<(EE * EE / 4 + 255) / 256, 256>>>(Wout, woh, wol, EE * EE / 4);

    // projections via HMMA tensor cores
    dim3 gg(EE / 128, MROWS / 128);   // (8, 64)
    gemm_split_kernel<<<gg, 256>>>(xqh, xql, wh,                   wl,                   bin,          qp, 2);
    gemm_split_kernel<<<gg, 256>>>(xkh, xkl, wh + (size_t)EE*EE,   wl + (size_t)EE*EE,   bin + EE,     kp, 2);
    gemm_split_kernel<<<gg, 256>>>(xvh, xvl, wh + 2*(size_t)EE*EE, wl + 2*(size_t)EE*EE, bin + 2*EE,   vp, 1);

    dim3 gs(SS / 128, SS / 128, BB * HH);
    scores_kernel<<<gs, 256>>>(qp, kp, pp);

    softmax_mean_kernel<<<BB * SS, 256>>>(pp, wout);

    dim3 gav(SS / 128, BB * HH);
    av_kernel<<<gav, 256>>>(pp, vp, ap);

    // out projection via HMMA tensor cores
    split_kernel<<<(MROWS * EE / 4 + 255) / 256, 256>>>(ap, ah, al, MROWS * EE / 4);
    gemm_split_kernel<<<gg, 256>>>(ah, al, woh, wol, bout, out, 0);
}

// round 7
// speedup vs baseline: 2.1798x; 1.2522x over previous
#include <cuda_runtime.h>
#include <cuda_bf16.h>
#include <math.h>
#include <math_constants.h>
#include <cstdint>

#define BB 4
#define SS 2048
#define EE 1024
#define HH 16
#define DD 64
#define MROWS (BB*SS)          // 8192

// -------- device scratch (statically allocated; no cudaMalloc allowed) -----
__device__ float g_p[268435456];        // [B,H,S,S] fp32 scores (1 GB)

// input / weight splits
__device__ __nv_bfloat16 g_xqh[8388608], g_xql[8388608];
__device__ __nv_bfloat16 g_xkh[8388608], g_xkl[8388608];
__device__ __nv_bfloat16 g_xvh[8388608], g_xvl[8388608];
__device__ __nv_bfloat16 g_wh[3145728],  g_wl[3145728];    // in_proj W [3E,E]
__device__ __nv_bfloat16 g_woh[1048576], g_wol[1048576];   // out_proj W [E,E]
// head-layout split planes [B,H,S,D]
__device__ __nv_bfloat16 g_qh[8388608],  g_ql[8388608];
__device__ __nv_bfloat16 g_kh[8388608],  g_kl[8388608];
__device__ __nv_bfloat16 g_vh[8388608],  g_vl[8388608];
// V transposed [B,H,D,S]
__device__ __nv_bfloat16 g_vth[8388608], g_vtl[8388608];
// probs split planes [B,H,S,S]
__device__ __nv_bfloat16 g_ph[268435456], g_pl[268435456];
// attention output split [B,S,E]
__device__ __nv_bfloat16 g_ah[8388608],  g_al[8388608];

// ============================ PTX helpers ==================================
__device__ __forceinline__ uint32_t smem_u32(const void* p) {
    uint32_t a;
    asm("{ .reg .u64 t; cvta.to.shared.u64 t, %1; cvt.u32.u64 %0, t; }"
        : "=r"(a) : "l"(p));
    return a;
}
__device__ __forceinline__ void ldsm_x4(uint32_t* r, uint32_t addr) {
    asm volatile("ldmatrix.sync.aligned.m8n8.x4.shared.b16 {%0,%1,%2,%3}, [%4];"
        : "=r"(r[0]), "=r"(r[1]), "=r"(r[2]), "=r"(r[3]) : "r"(addr));
}
__device__ __forceinline__ void mma_bf16(float* d, const uint32_t* a, const uint32_t* b) {
    asm volatile("mma.sync.aligned.m16n8k16.row.col.f32.bf16.bf16.f32 "
        "{%0,%1,%2,%3}, {%4,%5,%6,%7}, {%8,%9}, {%0,%1,%2,%3};"
        : "+f"(d[0]), "+f"(d[1]), "+f"(d[2]), "+f"(d[3])
        : "r"(a[0]), "r"(a[1]), "r"(a[2]), "r"(a[3]), "r"(b[0]), "r"(b[1]));
}
__device__ __forceinline__ void split2(float v, __nv_bfloat16& h, __nv_bfloat16& l) {
    h = __float2bfloat16_rn(v);
    l = __float2bfloat16_rn(v - __bfloat162float(h));
}

#define LDA 40   // smem row stride in halves (80B -> conflict-free LDSM)

// ============================ split kernel =================================
__global__ void __launch_bounds__(256)
split_kernel(const float* __restrict__ src,
             __nv_bfloat16* __restrict__ hi,
             __nv_bfloat16* __restrict__ lo, int n4)
{
    int i = blockIdx.x * 256 + threadIdx.x;
    if (i >= n4) return;
    float4 x = ((const float4*)src)[i];
    __nv_bfloat16 h0, h1, h2, h3, l0, l1, l2, l3;
    split2(x.x, h0, l0); split2(x.y, h1, l1);
    split2(x.z, h2, l2); split2(x.w, h3, l3);
    uint2 hv, lv;
    hv.x = (uint32_t)__bfloat16_as_ushort(h0) | ((uint32_t)__bfloat16_as_ushort(h1) << 16);
    hv.y = (uint32_t)__bfloat16_as_ushort(h2) | ((uint32_t)__bfloat16_as_ushort(h3) << 16);
    lv.x = (uint32_t)__bfloat16_as_ushort(l0) | ((uint32_t)__bfloat16_as_ushort(l1) << 16);
    lv.y = (uint32_t)__bfloat16_as_ushort(l2) | ((uint32_t)__bfloat16_as_ushort(l3) << 16);
    *(uint2*)(hi + (size_t)i * 4) = hv;
    *(uint2*)(lo + (size_t)i * 4) = lv;
}

// ============================ HMMA GEMM (projections) ======================
// C[m,n] = sum_k A[m,k]*B[n,k] + bias[n]; block 128x128, 8 warps (2m x 4n).
// mode 0: fp32 row-major [M,1024] to dst32
// mode 1: split planes, head scatter [B,H,S,D]
// mode 2: mode 1 + RoPE
__global__ void __launch_bounds__(256)
gemm_split_kernel(const __nv_bfloat16* __restrict__ Ah_,
                  const __nv_bfloat16* __restrict__ Al_,
                  const __nv_bfloat16* __restrict__ Bh_,
                  const __nv_bfloat16* __restrict__ Bl_,
                  const float* __restrict__ bias,
                  float* __restrict__ dst32,
                  __nv_bfloat16* __restrict__ dsth,
                  __nv_bfloat16* __restrict__ dstl, int mode)
{
    __shared__ __nv_bfloat16 sAh[128 * LDA], sAl[128 * LDA];
    __shared__ __nv_bfloat16 sBh[128 * LDA], sBl[128 * LDA];
    const int tid = threadIdx.x;
    const int w = tid >> 5, lane = tid & 31;
    const int wm = w & 1, wn = w >> 1;
    const int row0 = blockIdx.y * 128, col0 = blockIdx.x * 128;

    float acc[4][4][4] = {};

    const int a_r = lane & 15;
    const int a_c = (lane >> 4) << 3;
    const int b_n = (lane & 7) + ((lane >> 4) & 1) * 8;
    const int b_k = ((lane >> 3) & 1) * 8;
    const int ld_r  = tid >> 2;
    const int ld_c8 = (tid & 3) << 3;

    for (int k0 = 0; k0 < EE; k0 += 32) {
        #pragma unroll
        for (int u = 0; u < 2; u++) {
            const int r = ld_r + u * 64;
            const size_t ga = (size_t)(row0 + r) * EE + k0 + ld_c8;
            const size_t gb = (size_t)(col0 + r) * EE + k0 + ld_c8;
            *(uint4*)&sAh[r * LDA + ld_c8] = *(const uint4*)(Ah_ + ga);
            *(uint4*)&sAl[r * LDA + ld_c8] = *(const uint4*)(Al_ + ga);
            *(uint4*)&sBh[r * LDA + ld_c8] = *(const uint4*)(Bh_ + gb);
            *(uint4*)&sBl[r * LDA + ld_c8] = *(const uint4*)(Bl_ + gb);
        }
        __syncthreads();
        #pragma unroll
        for (int ks = 0; ks < 32; ks += 16) {
            uint32_t bfh[4][2], bfl[4][2];
            #pragma unroll
            for (int pr = 0; pr < 2; pr++) {
                const int nrow = wn * 32 + pr * 16 + b_n;
                uint32_t t[4];
                ldsm_x4(t, smem_u32(&sBh[nrow * LDA + ks + b_k]));
                bfh[2*pr][0] = t[0]; bfh[2*pr][1] = t[1];
                bfh[2*pr+1][0] = t[2]; bfh[2*pr+1][1] = t[3];
                ldsm_x4(t, smem_u32(&sBl[nrow * LDA + ks + b_k]));
                bfl[2*pr][0] = t[0]; bfl[2*pr][1] = t[1];
                bfl[2*pr+1][0] = t[2]; bfl[2*pr+1][1] = t[3];
            }
            uint32_t af[4][4];
            #pragma unroll
            for (int mt = 0; mt < 4; mt++)
                ldsm_x4(af[mt], smem_u32(&sAh[(wm*64 + mt*16 + a_r) * LDA + ks + a_c]));
            #pragma unroll
            for (int mt = 0; mt < 4; mt++)
                #pragma unroll
                for (int nt = 0; nt < 4; nt++) {
                    mma_bf16(acc[mt][nt], af[mt], bfh[nt]);
                    mma_bf16(acc[mt][nt], af[mt], bfl[nt]);
                }
            #pragma unroll
            for (int mt = 0; mt < 4; mt++)
                ldsm_x4(af[mt], smem_u32(&sAl[(wm*64 + mt*16 + a_r) * LDA + ks + a_c]));
            #pragma unroll
            for (int mt = 0; mt < 4; mt++)
                #pragma unroll
                for (int nt = 0; nt < 4; nt++)
                    mma_bf16(acc[mt][nt], af[mt], bfh[nt]);
        }
        __syncthreads();
    }

    const int r4 = lane >> 2, c2 = (lane & 3) << 1;
    float bs0[4], bs1[4], invs[4];
    #pragma unroll
    for (int nt = 0; nt < 4; nt++) {
        const int col = col0 + wn * 32 + nt * 8 + c2;
        bs0[nt] = bias[col];
        bs1[nt] = bias[col + 1];
        invs[nt] = expf(-(float)((col & 63) >> 1) * 0.28782313662425567f);
    }

    #pragma unroll
    for (int mt = 0; mt < 4; mt++) {
        #pragma unroll
        for (int rh = 0; rh < 2; rh++) {
            const int m = row0 + wm * 64 + mt * 16 + rh * 8 + r4;
            const int b = m >> 11, s = m & 2047;
            #pragma unroll
            for (int nt = 0; nt < 4; nt++) {
                const int col = col0 + wn * 32 + nt * 8 + c2;
                float v0 = acc[mt][nt][rh * 2 + 0] + bs0[nt];
                float v1 = acc[mt][nt][rh * 2 + 1] + bs1[nt];
                if (mode == 0) {
                    *(float2*)(dst32 + (size_t)m * EE + col) = make_float2(v0, v1);
                } else {
                    if (mode == 2) {
                        float sn, cs;
                        sincosf((float)s * invs[nt], &sn, &cs);
                        const float t0 = v0, t1 = v1;
                        v0 = t0 * cs - t1 * sn;
                        v1 = t1 * cs + t0 * sn;
                    }
                    const int h = col >> 6, d0 = col & 63;
                    const size_t off = ((size_t)(b * HH + h) * SS + s) * DD + d0;
                    __nv_bfloat16 h0, h1, l0, l1;
                    split2(v0, h0, l0); split2(v1, h1, l1);
                    *(__nv_bfloat162*)(dsth + off) = __nv_bfloat162(h0, h1);
                    *(__nv_bfloat162*)(dstl + off) = __nv_bfloat162(l0, l1);
                }
            }
        }
    }
}

// ============================ V transpose ==================================
// Vh/Vl [bh][s][d] -> Vth/Vtl [bh][d][s], 64x64 tiles
__global__ void __launch_bounds__(256)
vtrans_kernel(const __nv_bfloat16* __restrict__ Vh,
              const __nv_bfloat16* __restrict__ Vl,
              __nv_bfloat16* __restrict__ Vth,
              __nv_bfloat16* __restrict__ Vtl)
{
    __shared__ __nv_bfloat16 th[64 * 72], tl[64 * 72];
    const int bh = blockIdx.y, s0 = blockIdx.x * 64;
    const size_t ibase = (size_t)bh * SS * DD + (size_t)s0 * DD;
    #pragma unroll
    for (int i = 0; i < 2; i++) {
        const int idx = threadIdx.x + i * 256;
        const int r = idx >> 3, c = (idx & 7) * 8;
        *(uint4*)&th[r * 72 + c] = *(const uint4*)(Vh + ibase + (size_t)r * DD + c);
        *(uint4*)&tl[r * 72 + c] = *(const uint4*)(Vl + ibase + (size_t)r * DD + c);
    }
    __syncthreads();
    const size_t obase = (size_t)bh * DD * SS + s0;
    #pragma unroll
    for (int i = 0; i < 2; i++) {
        const int idx = threadIdx.x + i * 256;
        const int d = idx >> 3, c = (idx & 7) * 8;
        __nv_bfloat16 oh[8], ol[8];
        #pragma unroll
        for (int j = 0; j < 8; j++) {
            oh[j] = th[(c + j) * 72 + d];
            ol[j] = tl[(c + j) * 72 + d];
        }
        *(uint4*)(Vth + obase + (size_t)d * SS + c) = *(uint4*)oh;
        *(uint4*)(Vtl + obase + (size_t)d * SS + c) = *(uint4*)ol;
    }
}

// ============================ scores HMMA ==================================
// P[bh,q,k] = 0.125 * sum_d Q[bh,q,d]*K[bh,k,d]
__global__ void __launch_bounds__(256)
scores_hmma_kernel(const __nv_bfloat16* __restrict__ Qh,
                   const __nv_bfloat16* __restrict__ Ql,
                   const __nv_bfloat16* __restrict__ Kh,
                   const __nv_bfloat16* __restrict__ Kl,
                   float* __restrict__ P)
{
    __shared__ __nv_bfloat16 sAh[128 * LDA], sAl[128 * LDA];
    __shared__ __nv_bfloat16 sBh[128 * LDA], sBl[128 * LDA];
    const int tid = threadIdx.x;
    const int w = tid >> 5, lane = tid & 31;
    const int wm = w & 1, wn = w >> 1;
    const int bh = blockIdx.z;
    const int q0 = blockIdx.y * 128, k0t = blockIdx.x * 128;
    const size_t base = (size_t)bh * SS * DD;

    float acc[4][4][4] = {};

    const int a_r = lane & 15;
    const int a_c = (lane >> 4) << 3;
    const int b_n = (lane & 7) + ((lane >> 4) & 1) * 8;
    const int b_k = ((lane >> 3) & 1) * 8;
    const int ld_r  = tid >> 2;
    const int ld_c8 = (tid & 3) << 3;

    for (int kc = 0; kc < DD; kc += 32) {
        #pragma unroll
        for (int u = 0; u < 2; u++) {
            const int r = ld_r + u * 64;
            const size_t ga = base + (size_t)(q0 + r) * DD + kc + ld_c8;
            const size_t gb = base + (size_t)(k0t + r) * DD + kc + ld_c8;
            *(uint4*)&sAh[r * LDA + ld_c8] = *(const uint4*)(Qh + ga);
            *(uint4*)&sAl[r * LDA + ld_c8] = *(const uint4*)(Ql + ga);
            *(uint4*)&sBh[r * LDA + ld_c8] = *(const uint4*)(Kh + gb);
            *(uint4*)&sBl[r * LDA + ld_c8] = *(const uint4*)(Kl + gb);
        }
        __syncthreads();
        #pragma unroll
        for (int ks = 0; ks < 32; ks += 16) {
            uint32_t bfh[4][2], bfl[4][2];
            #pragma unroll
            for (int pr = 0; pr < 2; pr++) {
                const int nrow = wn * 32 + pr * 16 + b_n;
                uint32_t t[4];
                ldsm_x4(t, smem_u32(&sBh[nrow * LDA + ks + b_k]));
                bfh[2*pr][0] = t[0]; bfh[2*pr][1] = t[1];
                bfh[2*pr+1][0] = t[2]; bfh[2*pr+1][1] = t[3];
                ldsm_x4(t, smem_u32(&sBl[nrow * LDA + ks + b_k]));
                bfl[2*pr][0] = t[0]; bfl[2*pr][1] = t[1];
                bfl[2*pr+1][0] = t[2]; bfl[2*pr+1][1] = t[3];
            }
            uint32_t af[4][4];
            #pragma unroll
            for (int mt = 0; mt < 4; mt++)
                ldsm_x4(af[mt], smem_u32(&sAh[(wm*64 + mt*16 + a_r) * LDA + ks + a_c]));
            #pragma unroll
            for (int mt = 0; mt < 4; mt++)
                #pragma unroll
                for (int nt = 0; nt < 4; nt++) {
                    mma_bf16(acc[mt][nt], af[mt], bfh[nt]);
                    mma_bf16(acc[mt][nt], af[mt], bfl[nt]);
                }
            #pragma unroll
            for (int mt = 0; mt < 4; mt++)
                ldsm_x4(af[mt], smem_u32(&sAl[(wm*64 + mt*16 + a_r) * LDA + ks + a_c]));
            #pragma unroll
            for (int mt = 0; mt < 4; mt++)
                #pragma unroll
                for (int nt = 0; nt < 4; nt++)
                    mma_bf16(acc[mt][nt], af[mt], bfh[nt]);
        }
        __syncthreads();
    }

    const int r4 = lane >> 2, c2 = (lane & 3) << 1;
    const size_t pbase = (size_t)bh * SS * SS;
    #pragma unroll
    for (int mt = 0; mt < 4; mt++) {
        #pragma unroll
        for (int rh = 0; rh < 2; rh++) {
            const int q = q0 + wm * 64 + mt * 16 + rh * 8 + r4;
            #pragma unroll
            for (int nt = 0; nt < 4; nt++) {
                const int kk = k0t + wn * 32 + nt * 8 + c2;
                *(float2*)(P + pbase + (size_t)q * SS + kk) =
                    make_float2(acc[mt][nt][rh*2] * 0.125f, acc[mt][nt][rh*2+1] * 0.125f);
            }
        }
    }
}

// ---------------------------------------------------------------------------
// fused softmax + head-mean; reads fp32 P, writes split-bf16 probs + wout
// ---------------------------------------------------------------------------
__global__ void __launch_bounds__(256)
softmax_mean_kernel(const float* __restrict__ P,
                    __nv_bfloat16* __restrict__ Ph,
                    __nv_bfloat16* __restrict__ Pl,
                    float* __restrict__ wout)
{
    const int bq = blockIdx.x;
    const int b = bq >> 11, q = bq & 2047;
    const int tid = threadIdx.x;
    const int lane = tid & 31, warp = tid >> 5;
    __shared__ float red[8];

    float macc[8] = {};

    for (int h = 0; h < HH; h++) {
        const size_t rowoff = ((size_t)(b * HH + h) * SS + q) * SS;
        const float* p = P + rowoff;

        float v[8];
        #pragma unroll
        for (int i = 0; i < 8; i++) v[i] = p[tid + (i << 8)];

        float m = v[0];
        #pragma unroll
        for (int i = 1; i < 8; i++) m = fmaxf(m, v[i]);
        #pragma unroll
        for (int o = 16; o; o >>= 1) m = fmaxf(m, __shfl_xor_sync(0xffffffffu, m, o));
        if (lane == 0) red[warp] = m;
        __syncthreads();
        if (tid < 32) {
            float t = (tid < 8) ? red[tid] : -CUDART_INF_F;
            #pragma unroll
            for (int o = 4; o; o >>= 1) t = fmaxf(t, __shfl_xor_sync(0xffffffffu, t, o));
            if (tid == 0) red[0] = t;
        }
        __syncthreads();
        m = red[0];
        __syncthreads();

        float sum = 0.f;
        #pragma unroll
        for (int i = 0; i < 8; i++) { v[i] = expf(v[i] - m); sum += v[i]; }
        #pragma unroll
        for (int o = 16; o; o >>= 1) sum += __shfl_xor_sync(0xffffffffu, sum, o);
        if (lane == 0) red[warp] = sum;
        __syncthreads();
        if (tid < 32) {
            float t = (tid < 8) ? red[tid] : 0.f;
            #pragma unroll
            for (int o = 4; o; o >>= 1) t += __shfl_xor_sync(0xffffffffu, t, o);
            if (tid == 0) red[0] = t;
        }
        __syncthreads();
        const float inv = 1.0f / red[0];
        #pragma unroll
        for (int i = 0; i < 8; i++) {
            v[i] *= inv;
            __nv_bfloat16 hi, lo;
            split2(v[i], hi, lo);
            Ph[rowoff + tid + (i << 8)] = hi;
            Pl[rowoff + tid + (i << 8)] = lo;
            macc[i] += v[i];
        }
        __syncthreads();
    }

    float* wo = wout + (size_t)bq * SS;
    #pragma unroll
    for (int i = 0; i < 8; i++) wo[tid + (i << 8)] = macc[i] * (1.0f / HH);
}

// ============================ av HMMA ======================================
// O[q,d] = sum_k P[q,k] * Vt[d,k]; block 128(q) x 64(d); 8 warps (2m x 4n),
// warp tile 64 x 16.  Writes att split planes [b][s][E].
__global__ void __launch_bounds__(256)
av_hmma_kernel(const __nv_bfloat16* __restrict__ Ph,
               const __nv_bfloat16* __restrict__ Pl,
               const __nv_bfloat16* __restrict__ Vth,
               const __nv_bfloat16* __restrict__ Vtl,
               __nv_bfloat16* __restrict__ Oh,
               __nv_bfloat16* __restrict__ Ol)
{
    __shared__ __nv_bfloat16 sAh[128 * LDA], sAl[128 * LDA];
    __shared__ __nv_bfloat16 sBh[64 * LDA],  sBl[64 * LDA];
    const int tid = threadIdx.x;
    const int w = tid >> 5, lane = tid & 31;
    const int wm = w & 1, wn = w >> 1;        // wn 0..3, warp n-tile 16
    const int bh = blockIdx.y;
    const int b = bh >> 4, h = bh & 15;
    const int q0 = blockIdx.x * 128;
    const size_t pbase = (size_t)bh * SS * SS;
    const size_t vtbase = (size_t)bh * DD * SS;

    float acc[4][2][4] = {};

    const int a_r = lane & 15;
    const int a_c = (lane >> 4) << 3;
    const int b_n = (lane & 7) + ((lane >> 4) & 1) * 8;
    const int b_k = ((lane >> 3) & 1) * 8;
    const int ld_r  = tid >> 2;
    const int ld_c8 = (tid & 3) << 3;

    for (int k0 = 0; k0 < SS; k0 += 32) {
        #pragma unroll
        for (int u = 0; u < 2; u++) {
            const int r = ld_r + u * 64;
            const size_t ga = pbase + (size_t)(q0 + r) * SS + k0 + ld_c8;
            *(uint4*)&sAh[r * LDA + ld_c8] = *(const uint4*)(Ph + ga);
            *(uint4*)&sAl[r * LDA + ld_c8] = *(const uint4*)(Pl + ga);
        }
        {
            const size_t gb = vtbase + (size_t)ld_r * SS + k0 + ld_c8;
            *(uint4*)&sBh[ld_r * LDA + ld_c8] = *(const uint4*)(Vth + gb);
            *(uint4*)&sBl[ld_r * LDA + ld_c8] = *(const uint4*)(Vtl + gb);
        }
        __syncthreads();
        #pragma unroll
        for (int ks = 0; ks < 32; ks += 16) {
            uint32_t bfh[2][2], bfl[2][2];
            {
                const int nrow = wn * 16 + b_n;
                uint32_t t[4];
                ldsm_x4(t, smem_u32(&sBh[nrow * LDA + ks + b_k]));
                bfh[0][0] = t[0]; bfh[0][1] = t[1];
                bfh[1][0] = t[2]; bfh[1][1] = t[3];
                ldsm_x4(t, smem_u32(&sBl[nrow * LDA + ks + b_k]));
                bfl[0][0] = t[0]; bfl[0][1] = t[1];
                bfl[1][0] = t[2]; bfl[1][1] = t[3];
            }
            uint32_t af[4][4];
            #pragma unroll
            for (int mt = 0; mt < 4; mt++)
                ldsm_x4(af[mt], smem_u32(&sAh[(wm*64 + mt*16 + a_r) * LDA + ks + a_c]));
            #pragma unroll
            for (int mt = 0; mt < 4; mt++)
                #pragma unroll
                for (int nt = 0; nt < 2; nt++) {
                    mma_bf16(acc[mt][nt], af[mt], bfh[nt]);
                    mma_bf16(acc[mt][nt], af[mt], bfl[nt]);
                }
            #pragma unroll
            for (int mt = 0; mt < 4; mt++)
                ldsm_x4(af[mt], smem_u32(&sAl[(wm*64 + mt*16 + a_r) * LDA + ks + a_c]));
            #pragma unroll
            for (int mt = 0; mt < 4; mt++)
                #pragma unroll
                for (int nt = 0; nt < 2; nt++)
                    mma_bf16(acc[mt][nt], af[mt], bfh[nt]);
        }
        __syncthreads();
    }

    const int r4 = lane >> 2, c2 = (lane & 3) << 1;
    #pragma unroll
    for (int mt = 0; mt < 4; mt++) {
        #pragma unroll
        for (int rh = 0; rh < 2; rh++) {
            const int s = q0 + wm * 64 + mt * 16 + rh * 8 + r4;
            #pragma unroll
            for (int nt = 0; nt < 2; nt++) {
                const int d = wn * 16 + nt * 8 + c2;
                const float v0 = acc[mt][nt][rh*2];
                const float v1 = acc[mt][nt][rh*2+1];
                __nv_bfloat16 h0, h1, l0, l1;
                split2(v0, h0, l0); split2(v1, h1, l1);
                const size_t off = ((size_t)b * SS + s) * EE + h * DD + d;
                *(__nv_bfloat162*)(Oh + off) = __nv_bfloat162(h0, h1);
                *(__nv_bfloat162*)(Ol + off) = __nv_bfloat162(l0, l1);
            }
        }
    }
}

// ---------------------------------------------------------------------------
extern "C" void kernel_launch(void* const* d_in, const int* in_sizes, int n_in,
                              void* d_out, int out_size)
{
    const float* query = (const float*)d_in[0];
    const float* key   = (const float*)d_in[1];
    const float* value = (const float*)d_in[2];
    const float* Win   = (const float*)d_in[3];   // [3E, E]
    const float* bin   = (const float*)d_in[4];   // [3E]
    const float* Wout  = (const float*)d_in[5];   // [E, E]
    const float* bout  = (const float*)d_in[6];   // [E]

    float* out  = (float*)d_out;                          // [B,S,E]
    float* wout = out + (size_t)BB * SS * EE;             // [B,S,S]

    float* pp;
    cudaGetSymbolAddress((void**)&pp, g_p);

    __nv_bfloat16 *xqh, *xql, *xkh, *xkl, *xvh, *xvl, *wh, *wl, *woh, *wol;
    __nv_bfloat16 *qh, *ql, *kh, *kl, *vh, *vl, *vth, *vtl, *ph, *pl, *ah, *al;
    cudaGetSymbolAddress((void**)&xqh, g_xqh);
    cudaGetSymbolAddress((void**)&xql, g_xql);
    cudaGetSymbolAddress((void**)&xkh, g_xkh);
    cudaGetSymbolAddress((void**)&xkl, g_xkl);
    cudaGetSymbolAddress((void**)&xvh, g_xvh);
    cudaGetSymbolAddress((void**)&xvl, g_xvl);
    cudaGetSymbolAddress((void**)&wh,  g_wh);
    cudaGetSymbolAddress((void**)&wl,  g_wl);
    cudaGetSymbolAddress((void**)&woh, g_woh);
    cudaGetSymbolAddress((void**)&wol, g_wol);
    cudaGetSymbolAddress((void**)&qh,  g_qh);
    cudaGetSymbolAddress((void**)&ql,  g_ql);
    cudaGetSymbolAddress((void**)&kh,  g_kh);
    cudaGetSymbolAddress((void**)&kl,  g_kl);
    cudaGetSymbolAddress((void**)&vh,  g_vh);
    cudaGetSymbolAddress((void**)&vl,  g_vl);
    cudaGetSymbolAddress((void**)&vth, g_vth);
    cudaGetSymbolAddress((void**)&vtl, g_vtl);
    cudaGetSymbolAddress((void**)&ph,  g_ph);
    cudaGetSymbolAddress((void**)&pl,  g_pl);
    cudaGetSymbolAddress((void**)&ah,  g_ah);
    cudaGetSymbolAddress((void**)&al,  g_al);

    // splits of inputs + weights
    split_kernel<<<(MROWS * EE / 4 + 255) / 256, 256>>>(query, xqh, xql, MROWS * EE / 4);
    split_kernel<<<(MROWS * EE / 4 + 255) / 256, 256>>>(key,   xkh, xkl, MROWS * EE / 4);
    split_kernel<<<(MROWS * EE / 4 + 255) / 256, 256>>>(value, xvh, xvl, MROWS * EE / 4);
    split_kernel<<<(3 * EE * EE / 4 + 255) / 256, 256>>>(Win,  wh,  wl,  3 * EE * EE / 4);
    split_kernel<<<(EE * EE / 4 + 255) / 256, 256>>>(Wout, woh, wol, EE * EE / 4);

    // projections -> split planes in head layout (RoPE fused for q,k)
    dim3 gg(EE / 128, MROWS / 128);   // (8, 64)
    gemm_split_kernel<<<gg, 256>>>(xqh, xql, wh,                   wl,                   bin,        nullptr, qh, ql, 2);
    gemm_split_kernel<<<gg, 256>>>(xkh, xkl, wh + (size_t)EE*EE,   wl + (size_t)EE*EE,   bin + EE,   nullptr, kh, kl, 2);
    gemm_split_kernel<<<gg, 256>>>(xvh, xvl, wh + 2*(size_t)EE*EE, wl + 2*(size_t)EE*EE, bin + 2*EE, nullptr, vh, vl, 1);

    // V transpose
    dim3 gt(SS / 64, BB * HH);
    vtrans_kernel<<<gt, 256>>>(vh, vl, vth, vtl);

    // scores via HMMA
    dim3 gs(SS / 128, SS / 128, BB * HH);
    scores_hmma_kernel<<<gs, 256>>>(qh, ql, kh, kl, pp);

    // softmax + head mean; probs out as split planes
    softmax_mean_kernel<<<BB * SS, 256>>>(pp, ph, pl, wout);

    // attn @ V via HMMA -> att split planes
    dim3 gav(SS / 128, BB * HH);
    av_hmma_kernel<<<gav, 256>>>(ph, pl, vth, vtl, ah, al);

    // out projection -> fp32 output
    gemm_split_kernel<<<gg, 256>>>(ah, al, woh, wol, bout, out, nullptr, nullptr, 0);
}

// round 8
// speedup vs baseline: 2.5219x; 1.1569x over previous
#include <cuda_runtime.h>
#include <cuda_bf16.h>
#include <math.h>
#include <math_constants.h>
#include <cstdint>

#define BB 4
#define SS 2048
#define EE 1024
#define HH 16
#define DD 64
#define MROWS (BB*SS)          // 8192

// -------- device scratch (statically allocated; no cudaMalloc allowed) -----
__device__ float g_p[268435456];        // [B,H,S,S] fp32 scores (1 GB)

__device__ __nv_bfloat16 g_xqh[8388608], g_xql[8388608];
__device__ __nv_bfloat16 g_xkh[8388608], g_xkl[8388608];
__device__ __nv_bfloat16 g_xvh[8388608], g_xvl[8388608];
__device__ __nv_bfloat16 g_wh[3145728],  g_wl[3145728];    // in_proj W [3E,E]
__device__ __nv_bfloat16 g_woh[1048576], g_wol[1048576];   // out_proj W [E,E]
__device__ __nv_bfloat16 g_qh[8388608],  g_ql[8388608];
__device__ __nv_bfloat16 g_kh[8388608],  g_kl[8388608];
__device__ __nv_bfloat16 g_vh[8388608],  g_vl[8388608];
__device__ __nv_bfloat16 g_vth[8388608], g_vtl[8388608];   // V^T [B,H,D,S]
__device__ __nv_bfloat16 g_ph[268435456], g_pl[268435456]; // probs split
__device__ __nv_bfloat16 g_ah[8388608],  g_al[8388608];    // att split

// ============================ PTX helpers ==================================
__device__ __forceinline__ uint32_t smem_u32(const void* p) {
    uint32_t a;
    asm("{ .reg .u64 t; cvta.to.shared.u64 t, %1; cvt.u32.u64 %0, t; }"
        : "=r"(a) : "l"(p));
    return a;
}
__device__ __forceinline__ void ldsm_x4(uint32_t* r, uint32_t addr) {
    asm volatile("ldmatrix.sync.aligned.m8n8.x4.shared.b16 {%0,%1,%2,%3}, [%4];"
        : "=r"(r[0]), "=r"(r[1]), "=r"(r[2]), "=r"(r[3]) : "r"(addr));
}
__device__ __forceinline__ void mma_bf16(float* d, const uint32_t* a, const uint32_t* b) {
    asm volatile("mma.sync.aligned.m16n8k16.row.col.f32.bf16.bf16.f32 "
        "{%0,%1,%2,%3}, {%4,%5,%6,%7}, {%8,%9}, {%0,%1,%2,%3};"
        : "+f"(d[0]), "+f"(d[1]), "+f"(d[2]), "+f"(d[3])
        : "r"(a[0]), "r"(a[1]), "r"(a[2]), "r"(a[3]), "r"(b[0]), "r"(b[1]));
}
__device__ __forceinline__ void split2(float v, __nv_bfloat16& h, __nv_bfloat16& l) {
    h = __float2bfloat16_rn(v);
    l = __float2bfloat16_rn(v - __bfloat162float(h));
}
#define CP16(dst, src) \
    asm volatile("cp.async.cg.shared.global [%0], [%1], 16;" :: "r"(dst), "l"(src))
#define CP_COMMIT() asm volatile("cp.async.commit_group;" ::: "memory")
#define CP_WAIT1()  asm volatile("cp.async.wait_group 1;" ::: "memory")
#define CP_WAIT0()  asm volatile("cp.async.wait_group 0;" ::: "memory")

#define LDA 40   // smem row stride in halves (80B -> conflict-free LDSM, 16B-mult)

// ============================ split kernel =================================
__global__ void __launch_bounds__(256)
split_kernel(const float* __restrict__ src,
             __nv_bfloat16* __restrict__ hi,
             __nv_bfloat16* __restrict__ lo, int n4)
{
    int i = blockIdx.x * 256 + threadIdx.x;
    if (i >= n4) return;
    float4 x = ((const float4*)src)[i];
    __nv_bfloat16 h0, h1, h2, h3, l0, l1, l2, l3;
    split2(x.x, h0, l0); split2(x.y, h1, l1);
    split2(x.z, h2, l2); split2(x.w, h3, l3);
    uint2 hv, lv;
    hv.x = (uint32_t)__bfloat16_as_ushort(h0) | ((uint32_t)__bfloat16_as_ushort(h1) << 16);
    hv.y = (uint32_t)__bfloat16_as_ushort(h2) | ((uint32_t)__bfloat16_as_ushort(h3) << 16);
    lv.x = (uint32_t)__bfloat16_as_ushort(l0) | ((uint32_t)__bfloat16_as_ushort(l1) << 16);
    lv.y = (uint32_t)__bfloat16_as_ushort(l2) | ((uint32_t)__bfloat16_as_ushort(l3) << 16);
    *(uint2*)(hi + (size_t)i * 4) = hv;
    *(uint2*)(lo + (size_t)i * 4) = lv;
}

// ============================ HMMA GEMM (projections) ======================
// 128x128 block, 8 warps (2m x 4n), K=1024 in 32 chunks, 2-stage cp.async.
#define GPL  (128 * LDA * 2)     // 10240 B per plane
#define GSTG (4 * GPL)           // 40960 B per stage
#define GDSM (2 * GSTG)          // 81920 B

__global__ void __launch_bounds__(256)
gemm_split_kernel(const __nv_bfloat16* __restrict__ Ah_,
                  const __nv_bfloat16* __restrict__ Al_,
                  const __nv_bfloat16* __restrict__ Bh_,
                  const __nv_bfloat16* __restrict__ Bl_,
                  const float* __restrict__ bias,
                  float* __restrict__ dst32,
                  __nv_bfloat16* __restrict__ dsth,
                  __nv_bfloat16* __restrict__ dstl, int mode)
{
    extern __shared__ char dsm[];
    const uint32_t sb = smem_u32(dsm);
    const int tid = threadIdx.x;
    const int w = tid >> 5, lane = tid & 31;
    const int wm = w & 1, wn = w >> 1;
    const int row0 = blockIdx.y * 128, col0 = blockIdx.x * 128;

    float acc[4][4][4] = {};

    const int a_r = lane & 15;
    const int a_c = (lane >> 4) << 3;
    const int b_n = (lane & 7) + ((lane >> 4) & 1) * 8;
    const int b_k = ((lane >> 3) & 1) * 8;
    const int ld_r  = tid >> 2;
    const int ld_c8 = (tid & 3) << 3;

    // stage prefetch
    auto prefetch = [&](int it, int stage) {
        const int k0 = it * 32;
        const uint32_t s0 = sb + stage * GSTG;
        #pragma unroll
        for (int u = 0; u < 2; u++) {
            const int r = ld_r + u * 64;
            const uint32_t off = (uint32_t)(r * LDA + ld_c8) * 2;
            const size_t ga = (size_t)(row0 + r) * EE + k0 + ld_c8;
            const size_t gb = (size_t)(col0 + r) * EE + k0 + ld_c8;
            CP16(s0 + off,           Ah_ + ga);
            CP16(s0 + GPL + off,     Al_ + ga);
            CP16(s0 + 2 * GPL + off, Bh_ + gb);
            CP16(s0 + 3 * GPL + off, Bl_ + gb);
        }
        CP_COMMIT();
    };

    prefetch(0, 0);
    for (int it = 0; it < 32; it++) {
        const int stage = it & 1;
        if (it + 1 < 32) { prefetch(it + 1, stage ^ 1); CP_WAIT1(); }
        else             { CP_WAIT0(); }
        __syncthreads();
        const uint32_t s0 = sb + stage * GSTG;
        #pragma unroll
        for (int ks = 0; ks < 32; ks += 16) {
            uint32_t bfh[4][2], bfl[4][2];
            #pragma unroll
            for (int pr = 0; pr < 2; pr++) {
                const int nrow = wn * 32 + pr * 16 + b_n;
                uint32_t t[4];
                ldsm_x4(t, s0 + 2 * GPL + (uint32_t)(nrow * LDA + ks + b_k) * 2);
                bfh[2*pr][0] = t[0]; bfh[2*pr][1] = t[1];
                bfh[2*pr+1][0] = t[2]; bfh[2*pr+1][1] = t[3];
                ldsm_x4(t, s0 + 3 * GPL + (uint32_t)(nrow * LDA + ks + b_k) * 2);
                bfl[2*pr][0] = t[0]; bfl[2*pr][1] = t[1];
                bfl[2*pr+1][0] = t[2]; bfl[2*pr+1][1] = t[3];
            }
            uint32_t af[4][4];
            #pragma unroll
            for (int mt = 0; mt < 4; mt++)
                ldsm_x4(af[mt], s0 + (uint32_t)((wm*64 + mt*16 + a_r) * LDA + ks + a_c) * 2);
            #pragma unroll
            for (int mt = 0; mt < 4; mt++)
                #pragma unroll
                for (int nt = 0; nt < 4; nt++) {
                    mma_bf16(acc[mt][nt], af[mt], bfh[nt]);
                    mma_bf16(acc[mt][nt], af[mt], bfl[nt]);
                }
            #pragma unroll
            for (int mt = 0; mt < 4; mt++)
                ldsm_x4(af[mt], s0 + GPL + (uint32_t)((wm*64 + mt*16 + a_r) * LDA + ks + a_c) * 2);
            #pragma unroll
            for (int mt = 0; mt < 4; mt++)
                #pragma unroll
                for (int nt = 0; nt < 4; nt++)
                    mma_bf16(acc[mt][nt], af[mt], bfh[nt]);
        }
        __syncthreads();
    }

    const int r4 = lane >> 2, c2 = (lane & 3) << 1;
    float bs0[4], bs1[4], invs[4];
    #pragma unroll
    for (int nt = 0; nt < 4; nt++) {
        const int col = col0 + wn * 32 + nt * 8 + c2;
        bs0[nt] = bias[col];
        bs1[nt] = bias[col + 1];
        invs[nt] = expf(-(float)((col & 63) >> 1) * 0.28782313662425567f);
    }

    #pragma unroll
    for (int mt = 0; mt < 4; mt++) {
        #pragma unroll
        for (int rh = 0; rh < 2; rh++) {
            const int m = row0 + wm * 64 + mt * 16 + rh * 8 + r4;
            const int b = m >> 11, s = m & 2047;
            #pragma unroll
            for (int nt = 0; nt < 4; nt++) {
                const int col = col0 + wn * 32 + nt * 8 + c2;
                float v0 = acc[mt][nt][rh * 2 + 0] + bs0[nt];
                float v1 = acc[mt][nt][rh * 2 + 1] + bs1[nt];
                if (mode == 0) {
                    *(float2*)(dst32 + (size_t)m * EE + col) = make_float2(v0, v1);
                } else {
                    if (mode == 2) {
                        float sn, cs;
                        sincosf((float)s * invs[nt], &sn, &cs);
                        const float t0 = v0, t1 = v1;
                        v0 = t0 * cs - t1 * sn;
                        v1 = t1 * cs + t0 * sn;
                    }
                    const int h = col >> 6, d0 = col & 63;
                    const size_t off = ((size_t)(b * HH + h) * SS + s) * DD + d0;
                    __nv_bfloat16 h0, h1, l0, l1;
                    split2(v0, h0, l0); split2(v1, h1, l1);
                    *(__nv_bfloat162*)(dsth + off) = __nv_bfloat162(h0, h1);
                    *(__nv_bfloat162*)(dstl + off) = __nv_bfloat162(l0, l1);
                }
            }
        }
    }
}

// ============================ V transpose ==================================
__global__ void __launch_bounds__(256)
vtrans_kernel(const __nv_bfloat16* __restrict__ Vh,
              const __nv_bfloat16* __restrict__ Vl,
              __nv_bfloat16* __restrict__ Vth,
              __nv_bfloat16* __restrict__ Vtl)
{
    __shared__ __nv_bfloat16 th[64 * 72], tl[64 * 72];
    const int bh = blockIdx.y, s0 = blockIdx.x * 64;
    const size_t ibase = (size_t)bh * SS * DD + (size_t)s0 * DD;
    #pragma unroll
    for (int i = 0; i < 2; i++) {
        const int idx = threadIdx.x + i * 256;
        const int r = idx >> 3, c = (idx & 7) * 8;
        *(uint4*)&th[r * 72 + c] = *(const uint4*)(Vh + ibase + (size_t)r * DD + c);
        *(uint4*)&tl[r * 72 + c] = *(const uint4*)(Vl + ibase + (size_t)r * DD + c);
    }
    __syncthreads();
    const size_t obase = (size_t)bh * DD * SS + s0;
    #pragma unroll
    for (int i = 0; i < 2; i++) {
        const int idx = threadIdx.x + i * 256;
        const int d = idx >> 3, c = (idx & 7) * 8;
        __nv_bfloat16 oh[8], ol[8];
        #pragma unroll
        for (int j = 0; j < 8; j++) {
            oh[j] = th[(c + j) * 72 + d];
            ol[j] = tl[(c + j) * 72 + d];
        }
        *(uint4*)(Vth + obase + (size_t)d * SS + c) = *(uint4*)oh;
        *(uint4*)(Vtl + obase + (size_t)d * SS + c) = *(uint4*)ol;
    }
}

// ============================ scores HMMA ==================================
// K=64: 2 chunks, 2-stage cp.async (stage layout same as gemm).
__global__ void __launch_bounds__(256)
scores_hmma_kernel(const __nv_bfloat16* __restrict__ Qh,
                   const __nv_bfloat16* __restrict__ Ql,
                   const __nv_bfloat16* __restrict__ Kh,
                   const __nv_bfloat16* __restrict__ Kl,
                   float* __restrict__ P)
{
    extern __shared__ char dsm[];
    const uint32_t sb = smem_u32(dsm);
    const int tid = threadIdx.x;
    const int w = tid >> 5, lane = tid & 31;
    const int wm = w & 1, wn = w >> 1;
    const int bh = blockIdx.z;
    const int q0 = blockIdx.y * 128, k0t = blockIdx.x * 128;
    const size_t base = (size_t)bh * SS * DD;

    float acc[4][4][4] = {};

    const int a_r = lane & 15;
    const int a_c = (lane >> 4) << 3;
    const int b_n = (lane & 7) + ((lane >> 4) & 1) * 8;
    const int b_k = ((lane >> 3) & 1) * 8;
    const int ld_r  = tid >> 2;
    const int ld_c8 = (tid & 3) << 3;

    auto prefetch = [&](int it, int stage) {
        const int kc = it * 32;
        const uint32_t s0 = sb + stage * GSTG;
        #pragma unroll
        for (int u = 0; u < 2; u++) {
            const int r = ld_r + u * 64;
            const uint32_t off = (uint32_t)(r * LDA + ld_c8) * 2;
            const size_t ga = base + (size_t)(q0 + r) * DD + kc + ld_c8;
            const size_t gb = base + (size_t)(k0t + r) * DD + kc + ld_c8;
            CP16(s0 + off,           Qh + ga);
            CP16(s0 + GPL + off,     Ql + ga);
            CP16(s0 + 2 * GPL + off, Kh + gb);
            CP16(s0 + 3 * GPL + off, Kl + gb);
        }
        CP_COMMIT();
    };

    prefetch(0, 0);
    for (int it = 0; it < 2; it++) {
        const int stage = it & 1;
        if (it + 1 < 2) { prefetch(it + 1, stage ^ 1); CP_WAIT1(); }
        else            { CP_WAIT0(); }
        __syncthreads();
        const uint32_t s0 = sb + stage * GSTG;
        #pragma unroll
        for (int ks = 0; ks < 32; ks += 16) {
            uint32_t bfh[4][2], bfl[4][2];
            #pragma unroll
            for (int pr = 0; pr < 2; pr++) {
                const int nrow = wn * 32 + pr * 16 + b_n;
                uint32_t t[4];
                ldsm_x4(t, s0 + 2 * GPL + (uint32_t)(nrow * LDA + ks + b_k) * 2);
                bfh[2*pr][0] = t[0]; bfh[2*pr][1] = t[1];
                bfh[2*pr+1][0] = t[2]; bfh[2*pr+1][1] = t[3];
                ldsm_x4(t, s0 + 3 * GPL + (uint32_t)(nrow * LDA + ks + b_k) * 2);
                bfl[2*pr][0] = t[0]; bfl[2*pr][1] = t[1];
                bfl[2*pr+1][0] = t[2]; bfl[2*pr+1][1] = t[3];
            }
            uint32_t af[4][4];
            #pragma unroll
            for (int mt = 0; mt < 4; mt++)
                ldsm_x4(af[mt], s0 + (uint32_t)((wm*64 + mt*16 + a_r) * LDA + ks + a_c) * 2);
            #pragma unroll
            for (int mt = 0; mt < 4; mt++)
                #pragma unroll
                for (int nt = 0; nt < 4; nt++) {
                    mma_bf16(acc[mt][nt], af[mt], bfh[nt]);
                    mma_bf16(acc[mt][nt], af[mt], bfl[nt]);
                }
            #pragma unroll
            for (int mt = 0; mt < 4; mt++)
                ldsm_x4(af[mt], s0 + GPL + (uint32_t)((wm*64 + mt*16 + a_r) * LDA + ks + a_c) * 2);
            #pragma unroll
            for (int mt = 0; mt < 4; mt++)
                #pragma unroll
                for (int nt = 0; nt < 4; nt++)
                    mma_bf16(acc[mt][nt], af[mt], bfh[nt]);
        }
        __syncthreads();
    }

    const int r4 = lane >> 2, c2 = (lane & 3) << 1;
    const size_t pbase = (size_t)bh * SS * SS;
    #pragma unroll
    for (int mt = 0; mt < 4; mt++) {
        #pragma unroll
        for (int rh = 0; rh < 2; rh++) {
            const int q = q0 + wm * 64 + mt * 16 + rh * 8 + r4;
            #pragma unroll
            for (int nt = 0; nt < 4; nt++) {
                const int kk = k0t + wn * 32 + nt * 8 + c2;
                *(float2*)(P + pbase + (size_t)q * SS + kk) =
                    make_float2(acc[mt][nt][rh*2] * 0.125f, acc[mt][nt][rh*2+1] * 0.125f);
            }
        }
    }
}

// ---------------------------------------------------------------------------
// fused softmax + head-mean; reads fp32 P, writes split-bf16 probs + wout
// ---------------------------------------------------------------------------
__global__ void __launch_bounds__(256)
softmax_mean_kernel(const float* __restrict__ P,
                    __nv_bfloat16* __restrict__ Ph,
                    __nv_bfloat16* __restrict__ Pl,
                    float* __restrict__ wout)
{
    const int bq = blockIdx.x;
    const int b = bq >> 11, q = bq & 2047;
    const int tid = threadIdx.x;
    const int lane = tid & 31, warp = tid >> 5;
    __shared__ float red[8];

    float macc[8] = {};

    for (int h = 0; h < HH; h++) {
        const size_t rowoff = ((size_t)(b * HH + h) * SS + q) * SS;
        const float* p = P + rowoff;

        float v[8];
        #pragma unroll
        for (int i = 0; i < 8; i++) v[i] = p[tid + (i << 8)];

        float m = v[0];
        #pragma unroll
        for (int i = 1; i < 8; i++) m = fmaxf(m, v[i]);
        #pragma unroll
        for (int o = 16; o; o >>= 1) m = fmaxf(m, __shfl_xor_sync(0xffffffffu, m, o));
        if (lane == 0) red[warp] = m;
        __syncthreads();
        if (tid < 32) {
            float t = (tid < 8) ? red[tid] : -CUDART_INF_F;
            #pragma unroll
            for (int o = 4; o; o >>= 1) t = fmaxf(t, __shfl_xor_sync(0xffffffffu, t, o));
            if (tid == 0) red[0] = t;
        }
        __syncthreads();
        m = red[0];
        __syncthreads();

        float sum = 0.f;
        #pragma unroll
        for (int i = 0; i < 8; i++) { v[i] = expf(v[i] - m); sum += v[i]; }
        #pragma unroll
        for (int o = 16; o; o >>= 1) sum += __shfl_xor_sync(0xffffffffu, sum, o);
        if (lane == 0) red[warp] = sum;
        __syncthreads();
        if (tid < 32) {
            float t = (tid < 8) ? red[tid] : 0.f;
            #pragma unroll
            for (int o = 4; o; o >>= 1) t += __shfl_xor_sync(0xffffffffu, t, o);
            if (tid == 0) red[0] = t;
        }
        __syncthreads();
        const float inv = 1.0f / red[0];
        #pragma unroll
        for (int i = 0; i < 8; i++) {
            v[i] *= inv;
            __nv_bfloat16 hi, lo;
            split2(v[i], hi, lo);
            Ph[rowoff + tid + (i << 8)] = hi;
            Pl[rowoff + tid + (i << 8)] = lo;
            macc[i] += v[i];
        }
        __syncthreads();
    }

    float* wo = wout + (size_t)bq * SS;
    #pragma unroll
    for (int i = 0; i < 8; i++) wo[tid + (i << 8)] = macc[i] * (1.0f / HH);
}

// ============================ av HMMA ======================================
// O[q,d] = sum_k P[q,k]*Vt[d,k]; block 128x64; 64 K-iters, 2-stage cp.async.
#define APL  (128 * LDA * 2)           // 10240
#define BPL  (64 * LDA * 2)            // 5120
#define ASTG (2 * APL + 2 * BPL)       // 30720
#define ADSM (2 * ASTG)                // 61440

__global__ void __launch_bounds__(256)
av_hmma_kernel(const __nv_bfloat16* __restrict__ Ph,
               const __nv_bfloat16* __restrict__ Pl,
               const __nv_bfloat16* __restrict__ Vth,
               const __nv_bfloat16* __restrict__ Vtl,
               __nv_bfloat16* __restrict__ Oh,
               __nv_bfloat16* __restrict__ Ol)
{
    extern __shared__ char dsm[];
    const uint32_t sb = smem_u32(dsm);
    const int tid = threadIdx.x;
    const int w = tid >> 5, lane = tid & 31;
    const int wm = w & 1, wn = w >> 1;
    const int bh = blockIdx.y;
    const int b = bh >> 4, h = bh & 15;
    const int q0 = blockIdx.x * 128;
    const size_t pbase = (size_t)bh * SS * SS;
    const size_t vtbase = (size_t)bh * DD * SS;

    float acc[4][2][4] = {};

    const int a_r = lane & 15;
    const int a_c = (lane >> 4) << 3;
    const int b_n = (lane & 7) + ((lane >> 4) & 1) * 8;
    const int b_k = ((lane >> 3) & 1) * 8;
    const int ld_r  = tid >> 2;
    const int ld_c8 = (tid & 3) << 3;

    auto prefetch = [&](int it, int stage) {
        const int k0 = it * 32;
        const uint32_t s0 = sb + stage * ASTG;
        #pragma unroll
        for (int u = 0; u < 2; u++) {
            const int r = ld_r + u * 64;
            const uint32_t off = (uint32_t)(r * LDA + ld_c8) * 2;
            const size_t ga = pbase + (size_t)(q0 + r) * SS + k0 + ld_c8;
            CP16(s0 + off,       Ph + ga);
            CP16(s0 + APL + off, Pl + ga);
        }
        {
            const uint32_t off = (uint32_t)(ld_r * LDA + ld_c8) * 2;
            const size_t gb = vtbase + (size_t)ld_r * SS + k0 + ld_c8;
            CP16(s0 + 2 * APL + off,       Vth + gb);
            CP16(s0 + 2 * APL + BPL + off, Vtl + gb);
        }
        CP_COMMIT();
    };

    prefetch(0, 0);
    for (int it = 0; it < 64; it++) {
        const int stage = it & 1;
        if (it + 1 < 64) { prefetch(it + 1, stage ^ 1); CP_WAIT1(); }
        else             { CP_WAIT0(); }
        __syncthreads();
        const uint32_t s0 = sb + stage * ASTG;
        #pragma unroll
        for (int ks = 0; ks < 32; ks += 16) {
            uint32_t bfh[2][2], bfl[2][2];
            {
                const int nrow = wn * 16 + b_n;
                uint32_t t[4];
                ldsm_x4(t, s0 + 2 * APL + (uint32_t)(nrow * LDA + ks + b_k) * 2);
                bfh[0][0] = t[0]; bfh[0][1] = t[1];
                bfh[1][0] = t[2]; bfh[1][1] = t[3];
                ldsm_x4(t, s0 + 2 * APL + BPL + (uint32_t)(nrow * LDA + ks + b_k) * 2);
                bfl[0][0] = t[0]; bfl[0][1] = t[1];
                bfl[1][0] = t[2]; bfl[1][1] = t[3];
            }
            uint32_t af[4][4];
            #pragma unroll
            for (int mt = 0; mt < 4; mt++)
                ldsm_x4(af[mt], s0 + (uint32_t)((wm*64 + mt*16 + a_r) * LDA + ks + a_c) * 2);
            #pragma unroll
            for (int mt = 0; mt < 4; mt++)
                #pragma unroll
                for (int nt = 0; nt < 2; nt++) {
                    mma_bf16(acc[mt][nt], af[mt], bfh[nt]);
                    mma_bf16(acc[mt][nt], af[mt], bfl[nt]);
                }
            #pragma unroll
            for (int mt = 0; mt < 4; mt++)
                ldsm_x4(af[mt], s0 + APL + (uint32_t)((wm*64 + mt*16 + a_r) * LDA + ks + a_c) * 2);
            #pragma unroll
            for (int mt = 0; mt < 4; mt++)
                #pragma unroll
                for (int nt = 0; nt < 2; nt++)
                    mma_bf16(acc[mt][nt], af[mt], bfh[nt]);
        }
        __syncthreads();
    }

    const int r4 = lane >> 2, c2 = (lane & 3) << 1;
    #pragma unroll
    for (int mt = 0; mt < 4; mt++) {
        #pragma unroll
        for (int rh = 0; rh < 2; rh++) {
            const int s = q0 + wm * 64 + mt * 16 + rh * 8 + r4;
            #pragma unroll
            for (int nt = 0; nt < 2; nt++) {
                const int d = wn * 16 + nt * 8 + c2;
                const float v0 = acc[mt][nt][rh*2];
                const float v1 = acc[mt][nt][rh*2+1];
                __nv_bfloat16 h0, h1, l0, l1;
                split2(v0, h0, l0); split2(v1, h1, l1);
                const size_t off = ((size_t)b * SS + s) * EE + h * DD + d;
                *(__nv_bfloat162*)(Oh + off) = __nv_bfloat162(h0, h1);
                *(__nv_bfloat162*)(Ol + off) = __nv_bfloat162(l0, l1);
            }
        }
    }
}

// ---------------------------------------------------------------------------
extern "C" void kernel_launch(void* const* d_in, const int* in_sizes, int n_in,
                              void* d_out, int out_size)
{
    const float* query = (const float*)d_in[0];
    const float* key   = (const float*)d_in[1];
    const float* value = (const float*)d_in[2];
    const float* Win   = (const float*)d_in[3];
    const float* bin   = (const float*)d_in[4];
    const float* Wout  = (const float*)d_in[5];
    const float* bout  = (const float*)d_in[6];

    float* out  = (float*)d_out;
    float* wout = out + (size_t)BB * SS * EE;

    float* pp;
    cudaGetSymbolAddress((void**)&pp, g_p);

    __nv_bfloat16 *xqh, *xql, *xkh, *xkl, *xvh, *xvl, *wh, *wl, *woh, *wol;
    __nv_bfloat16 *qh, *ql, *kh, *kl, *vh, *vl, *vth, *vtl, *ph, *pl, *ah, *al;
    cudaGetSymbolAddress((void**)&xqh, g_xqh);
    cudaGetSymbolAddress((void**)&xql, g_xql);
    cudaGetSymbolAddress((void**)&xkh, g_xkh);
    cudaGetSymbolAddress((void**)&xkl, g_xkl);
    cudaGetSymbolAddress((void**)&xvh, g_xvh);
    cudaGetSymbolAddress((void**)&xvl, g_xvl);
    cudaGetSymbolAddress((void**)&wh,  g_wh);
    cudaGetSymbolAddress((void**)&wl,  g_wl);
    cudaGetSymbolAddress((void**)&woh, g_woh);
    cudaGetSymbolAddress((void**)&wol, g_wol);
    cudaGetSymbolAddress((void**)&qh,  g_qh);
    cudaGetSymbolAddress((void**)&ql,  g_ql);
    cudaGetSymbolAddress((void**)&kh,  g_kh);
    cudaGetSymbolAddress((void**)&kl,  g_kl);
    cudaGetSymbolAddress((void**)&vh,  g_vh);
    cudaGetSymbolAddress((void**)&vl,  g_vl);
    cudaGetSymbolAddress((void**)&vth, g_vth);
    cudaGetSymbolAddress((void**)&vtl, g_vtl);
    cudaGetSymbolAddress((void**)&ph,  g_ph);
    cudaGetSymbolAddress((void**)&pl,  g_pl);
    cudaGetSymbolAddress((void**)&ah,  g_ah);
    cudaGetSymbolAddress((void**)&al,  g_al);

    cudaFuncSetAttribute(gemm_split_kernel,
                         cudaFuncAttributeMaxDynamicSharedMemorySize, GDSM);
    cudaFuncSetAttribute(scores_hmma_kernel,
                         cudaFuncAttributeMaxDynamicSharedMemorySize, GDSM);
    cudaFuncSetAttribute(av_hmma_kernel,
                         cudaFuncAttributeMaxDynamicSharedMemorySize, ADSM);

    // splits of inputs + weights
    split_kernel<<<(MROWS * EE / 4 + 255) / 256, 256>>>(query, xqh, xql, MROWS * EE / 4);
    split_kernel<<<(MROWS * EE / 4 + 255) / 256, 256>>>(key,   xkh, xkl, MROWS * EE / 4);
    split_kernel<<<(MROWS * EE / 4 + 255) / 256, 256>>>(value, xvh, xvl, MROWS * EE / 4);
    split_kernel<<<(3 * EE * EE / 4 + 255) / 256, 256>>>(Win,  wh,  wl,  3 * EE * EE / 4);
    split_kernel<<<(EE * EE / 4 + 255) / 256, 256>>>(Wout, woh, wol, EE * EE / 4);

    // projections (RoPE fused for q,k)
    dim3 gg(EE / 128, MROWS / 128);
    gemm_split_kernel<<<gg, 256, GDSM>>>(xqh, xql, wh,                   wl,                   bin,        nullptr, qh, ql, 2);
    gemm_split_kernel<<<gg, 256, GDSM>>>(xkh, xkl, wh + (size_t)EE*EE,   wl + (size_t)EE*EE,   bin + EE,   nullptr, kh, kl, 2);
    gemm_split_kernel<<<gg, 256, GDSM>>>(xvh, xvl, wh + 2*(size_t)EE*EE, wl + 2*(size_t)EE*EE, bin + 2*EE, nullptr, vh, vl, 1);

    // V transpose
    dim3 gt(SS / 64, BB * HH);
    vtrans_kernel<<<gt, 256>>>(vh, vl, vth, vtl);

    // scores
    dim3 gs(SS / 128, SS / 128, BB * HH);
    scores_hmma_kernel<<<gs, 256, GDSM>>>(qh, ql, kh, kl, pp);

    // softmax + head mean
    softmax_mean_kernel<<<BB * SS, 256>>>(pp, ph, pl, wout);

    // attn @ V
    dim3 gav(SS / 128, BB * HH);
    av_hmma_kernel<<<gav, 256, ADSM>>>(ph, pl, vth, vtl, ah, al);

    // out projection
    gemm_split_kernel<<<gg, 256, GDSM>>>(ah, al, woh, wol, bout, out, nullptr, nullptr, 0);
}